// round 7
// baseline (speedup 1.0000x reference)
#include <cuda_runtime.h>
#include <cuda_bf16.h>
#include <cstdint>

#define NNODES 10000
#define NEDGES 160000
#define HID    512
#define NOUT   16
#define QMAX   16320.0f     // 127*128 + 64

// ---------------- device scratch ----------------
__device__ float g_h[NNODES * HID];          // GEMM output fp32
__device__ float g_a[NNODES * HID];          // layer-2 agg output fp32
__device__ char  g_xq1[NNODES * HID];        // x int8 hi plane
__device__ char  g_xq0[NNODES * HID];        // x int8 lo plane
__device__ char  g_aq1[NNODES * HID];        // agg1 int8 hi plane
__device__ char  g_aq0[NNODES * HID];        // agg1 int8 lo plane
__device__ char  g_bq1[2 * HID * HID];       // W^T int8 hi (layer 0/1)
__device__ char  g_bq0[2 * HID * HID];       // W^T int8 lo
__device__ float g_sa1[NNODES];              // delta for x rows
__device__ float g_sa2[NNODES];              // delta for agg1 rows
__device__ float g_sb[2 * HID];              // delta for W cols (B^T rows)
__device__ unsigned int g_wmax[2 * HID];     // col abs-max (as uint-float)
__device__ float g_dinv[NNODES];
__device__ int   g_degcnt[NNODES];
__device__ int   g_fill[NNODES];
__device__ int   g_rowstart[NNODES];
__device__ int   g_total;
__device__ int   g_srcv[NEDGES];
__device__ int   g_dsttmp[NEDGES];
__device__ int   g_adjout[NEDGES];

__device__ __forceinline__ uint32_t smem_to_u32(const void* p) {
    uint32_t a;
    asm("{ .reg .u64 t; cvta.to.shared.u64 t, %1; cvt.u32.u64 %0, t; }" : "=r"(a) : "l"(p));
    return a;
}
__device__ __forceinline__ void cp_async16(uint32_t dst, const void* src, bool pred) {
    int sz = pred ? 16 : 0;
    asm volatile("cp.async.cg.shared.global [%0], [%1], 16, %2;\n"
                 :: "r"(dst), "l"(src), "r"(sz));
}
__device__ __forceinline__ void cp_commit() {
    asm volatile("cp.async.commit_group;\n" ::: "memory");
}
template <int N>
__device__ __forceinline__ void cp_wait() {
    asm volatile("cp.async.wait_group %0;\n" :: "n"(N) : "memory");
}
__device__ __forceinline__ void ldsm4(uint32_t addr, uint32_t r[4]) {
    asm volatile("ldmatrix.sync.aligned.m8n8.x4.shared.b16 {%0,%1,%2,%3}, [%4];"
                 : "=r"(r[0]), "=r"(r[1]), "=r"(r[2]), "=r"(r[3]) : "r"(addr));
}
__device__ __forceinline__ void imma(int acc[4], const uint32_t a[4], uint32_t b0, uint32_t b1) {
    asm volatile("mma.sync.aligned.m16n8k32.row.col.s32.s8.s8.s32 "
                 "{%0,%1,%2,%3}, {%4,%5,%6,%7}, {%8,%9}, {%0,%1,%2,%3};"
                 : "+r"(acc[0]), "+r"(acc[1]), "+r"(acc[2]), "+r"(acc[3])
                 : "r"(a[0]), "r"(a[1]), "r"(a[2]), "r"(a[3]), "r"(b0), "r"(b1));
}
__device__ __forceinline__ void quant2(float v, float inv, int& q1, int& q0) {
    int q = __float2int_rn(v * inv);
    int hi = (q + 64) >> 7;
    hi = max(-128, min(127, hi));
    q1 = hi;
    q0 = q - (hi << 7);
}

// ---------------- launch 0: x row-quantize + zero counters ----------------
__global__ __launch_bounds__(128) void xq_kernel(const float* __restrict__ x) {
    __shared__ float red[128];
    int v = blockIdx.x, t = threadIdx.x;
    if (t == 0) { g_degcnt[v] = 0; g_fill[v] = 0; }
    if (v < 2 * HID && t == 1) g_wmax[v] = 0u;
    if (v == 0 && t == 2) g_total = 0;

    float4 a = ((const float4*)x)[(size_t)v * (HID / 4) + t];
    float m = fmaxf(fmaxf(fabsf(a.x), fabsf(a.y)), fmaxf(fabsf(a.z), fabsf(a.w)));
    red[t] = m;
    __syncthreads();
    for (int o = 64; o > 0; o >>= 1) {
        if (t < o) red[t] = fmaxf(red[t], red[t + o]);
        __syncthreads();
    }
    float mx = red[0];
    float inv = (mx > 1e-30f) ? (QMAX / mx) : 0.0f;
    int q1x, q0x, q1y, q0y, q1z, q0z, q1w, q0w;
    quant2(a.x, inv, q1x, q0x); quant2(a.y, inv, q1y, q0y);
    quant2(a.z, inv, q1z, q0z); quant2(a.w, inv, q1w, q0w);
    size_t o4 = (size_t)v * HID + t * 4;
    *(char4*)&g_xq1[o4] = make_char4((char)q1x, (char)q1y, (char)q1z, (char)q1w);
    *(char4*)&g_xq0[o4] = make_char4((char)q0x, (char)q0y, (char)q0z, (char)q0w);
    if (t == 0) g_sa1[v] = mx / QMAX;
}

// ---------------- launch 1: W column abs-max ----------------
__global__ __launch_bounds__(512) void wmax_kernel(const float* __restrict__ W1,
                                                   const float* __restrict__ W2) {
    const float* W = blockIdx.y ? W2 : W1;
    int n = threadIdx.x;
    int k0 = blockIdx.x * 64;
    float m = 0.0f;
    for (int k = 0; k < 64; k++)
        m = fmaxf(m, fabsf(W[(size_t)(k0 + k) * HID + n]));
    atomicMax(&g_wmax[blockIdx.y * HID + n], __float_as_uint(m));
}

// ---------------- launch 2: W transpose + quantize ----------------
__global__ void wq_kernel(const float* __restrict__ W1, const float* __restrict__ W2) {
    __shared__ float tile[32][33];
    int z = blockIdx.z;
    const float* W = z ? W2 : W1;
    char* Bq1 = g_bq1 + (size_t)z * HID * HID;
    char* Bq0 = g_bq0 + (size_t)z * HID * HID;
    int n0 = blockIdx.x * 32, k0 = blockIdx.y * 32;
    int tx = threadIdx.x, ty = threadIdx.y;
#pragma unroll
    for (int j = 0; j < 32; j += 8)
        tile[ty + j][tx] = W[(size_t)(k0 + ty + j) * HID + n0 + tx];
    __syncthreads();
#pragma unroll
    for (int j = 0; j < 32; j += 8) {
        int n = n0 + ty + j;
        float mx = __uint_as_float(g_wmax[z * HID + n]);
        float inv = (mx > 1e-30f) ? (QMAX / mx) : 0.0f;
        float v = tile[tx][ty + j];
        int q1, q0;
        quant2(v, inv, q1, q0);
        size_t o = (size_t)n * HID + k0 + tx;
        Bq1[o] = (char)q1;
        Bq0[o] = (char)q0;
        if (blockIdx.y == 0 && tx == 0)
            g_sb[z * HID + n] = mx / QMAX;
    }
}

// ---------------- launch 3: edge convert + degree count ----------------
__global__ void convert_kernel(const void* __restrict__ ei, int E) {
    __shared__ int s_is64;
    if (threadIdx.x == 0) {
        const unsigned int* p = (const unsigned int*)ei;
        int is64 = 1;
        for (int i = 1; i < 128; i += 2)
            if (p[i] != 0u) { is64 = 0; break; }
        s_is64 = is64;
    }
    __syncthreads();
    int e = blockIdx.x * blockDim.x + threadIdx.x;
    if (e >= E) return;
    int s, d;
    if (s_is64) {
        const long long* p = (const long long*)ei;
        s = (int)p[e]; d = (int)p[E + e];
    } else {
        const int* p = (const int*)ei;
        s = p[e]; d = p[E + e];
    }
    g_srcv[e] = s;
    g_dsttmp[e] = d;
    atomicAdd(&g_degcnt[d], 1);
}

// ---------------- launch 4: row starts + dinv ----------------
__global__ void rowstart_kernel(int M) {
    int i = blockIdx.x * blockDim.x + threadIdx.x;
    if (i >= M) return;
    int d = g_degcnt[i];
    g_dinv[i] = rsqrtf((float)d + 1.0f);
    g_rowstart[i] = atomicAdd(&g_total, d);
}

// ---------------- launch 5: adjacency fill ----------------
__global__ void fill_kernel(int E) {
    int e = blockIdx.x * blockDim.x + threadIdx.x;
    if (e >= E) return;
    int d = g_dsttmp[e];
    int s = g_srcv[e];
    int p = atomicAdd(&g_fill[d], 1);
    g_adjout[g_rowstart[d] + p] = s;
}

// ---------------- two-plane int8 IMMA GEMM: C[M,512] = A @ B^T ----------------
// Planes: A1,A0 [M,512] s8 row-major; B1,B0 [512,512] s8 (B^T, K-major).
// C = sA[i]*sB[j]*(16384*S11 + 128*(S10+S01)). Grid (4, ceil(M/128)), 256 thr.
#define TSTRIDE 40                    // b16 units per smem row (32 data + 8 pad)
#define TILEB   (128 * TSTRIDE * 2)   // 10240 bytes per 128x64B tile
#define STAGEB  (4 * TILEB)

__global__ __launch_bounds__(256) void gemm_imma(const char* __restrict__ Aq1,
                                                 const char* __restrict__ Aq0,
                                                 const char* __restrict__ Bq1,
                                                 const char* __restrict__ Bq0,
                                                 const float* __restrict__ sA,
                                                 const float* __restrict__ sB,
                                                 float* __restrict__ C, int M) {
    extern __shared__ char dynsm[];
    uint32_t sbase = smem_to_u32(dynsm);

    int tid = threadIdx.x;
    int wid = tid >> 5, lane = tid & 31;
    int bm = blockIdx.y * 128, bn = blockIdx.x * 128;
    int wm = (wid >> 1) * 32;
    int wn = (wid & 1) * 64;

    int accH[2][8][4], accX[2][8][4];
#pragma unroll
    for (int i = 0; i < 2; i++)
#pragma unroll
        for (int n = 0; n < 8; n++)
#pragma unroll
            for (int q = 0; q < 4; q++) { accH[i][n][q] = 0; accX[i][n][q] = 0; }

    int a_row = (lane & 7) + ((lane >> 3) & 1) * 8;
    int a_col = (lane >> 4) * 8;
    int b_row = (lane & 7) + (lane >> 4) * 8;
    int b_col = ((lane >> 3) & 1) * 8;

    int row0 = tid >> 1, q0 = (tid & 1) * 2;
    bool avalid = (bm + row0) < M;

    auto issue = [&](int c, int s) {
        uint32_t st = sbase + s * STAGEB;
        size_t gA = (size_t)(bm + row0) * HID + c * 64;
        size_t gB = (size_t)(bn + row0) * HID + c * 64;
        uint32_t soff = (uint32_t)row0 * (TSTRIDE * 2);
#pragma unroll
        for (int q = 0; q < 2; q++) {
            uint32_t dq = soff + (q0 + q) * 16;
            cp_async16(st + dq, Aq1 + gA + (q0 + q) * 16, avalid);
            cp_async16(st + TILEB + dq, Aq0 + gA + (q0 + q) * 16, avalid);
            cp_async16(st + 2 * TILEB + dq, Bq1 + gB + (q0 + q) * 16, true);
            cp_async16(st + 3 * TILEB + dq, Bq0 + gB + (q0 + q) * 16, true);
        }
        cp_commit();
    };

    issue(0, 0);

    for (int c = 0; c < HID / 64; c++) {
        int s = c & 1;
        if (c + 1 < HID / 64) {
            issue(c + 1, s ^ 1);
            cp_wait<1>();
        } else {
            cp_wait<0>();
        }
        __syncthreads();

        uint32_t st = sbase + s * STAGEB;
        uint32_t bA1 = st, bA0 = st + TILEB, bB1 = st + 2 * TILEB, bB0 = st + 3 * TILEB;

#pragma unroll
        for (int ks = 0; ks < 2; ks++) {
            int k0 = ks * 16;    // b16 units = 32 int8
            uint32_t a1f[2][4], a0f[2][4], b1f[4][4], b0f[4][4];
#pragma unroll
            for (int i = 0; i < 2; i++) {
                uint32_t off = ((uint32_t)(wm + i * 16 + a_row) * TSTRIDE + k0 + a_col) * 2;
                ldsm4(bA1 + off, a1f[i]);
                ldsm4(bA0 + off, a0f[i]);
            }
#pragma unroll
            for (int j = 0; j < 4; j++) {
                uint32_t off = ((uint32_t)(wn + j * 16 + b_row) * TSTRIDE + k0 + b_col) * 2;
                ldsm4(bB1 + off, b1f[j]);
                ldsm4(bB0 + off, b0f[j]);
            }

#pragma unroll
            for (int i = 0; i < 2; i++) {
#pragma unroll
                for (int n = 0; n < 8; n++) {
                    uint32_t h0 = b1f[n >> 1][(n & 1) * 2];
                    uint32_t h1 = b1f[n >> 1][(n & 1) * 2 + 1];
                    uint32_t l0 = b0f[n >> 1][(n & 1) * 2];
                    uint32_t l1 = b0f[n >> 1][(n & 1) * 2 + 1];
                    imma(accH[i][n], a1f[i], h0, h1);   // S11
                    imma(accX[i][n], a1f[i], l0, l1);   // S10
                    imma(accX[i][n], a0f[i], h0, h1);   // S01
                }
            }
        }
        __syncthreads();
    }

    // ---- dequant epilogue ----
#pragma unroll
    for (int i = 0; i < 2; i++) {
        int r0 = bm + wm + i * 16 + (lane >> 2);
        int r1 = r0 + 8;
        float s0 = (r0 < M) ? sA[r0] : 0.0f;
        float s1 = (r1 < M) ? sA[r1] : 0.0f;
#pragma unroll
        for (int n = 0; n < 8; n++) {
            int col = bn + wn + n * 8 + (lane & 3) * 2;
            float2 sb2 = *(const float2*)&sB[col];
            if (r0 < M) {
                float2 o;
                o.x = s0 * sb2.x * (16384.0f * (float)accH[i][n][0] + 128.0f * (float)accX[i][n][0]);
                o.y = s0 * sb2.y * (16384.0f * (float)accH[i][n][1] + 128.0f * (float)accX[i][n][1]);
                *(float2*)&C[(size_t)r0 * HID + col] = o;
            }
            if (r1 < M) {
                float2 o;
                o.x = s1 * sb2.x * (16384.0f * (float)accH[i][n][2] + 128.0f * (float)accX[i][n][2]);
                o.y = s1 * sb2.y * (16384.0f * (float)accH[i][n][3] + 128.0f * (float)accX[i][n][3]);
                *(float2*)&C[(size_t)r1 * HID + col] = o;
            }
        }
    }
}

// ---------------- aggregation layer 1: gather + bias + relu + row-quantize ----
__global__ __launch_bounds__(128) void agg_q_kernel(const float* __restrict__ h,
                                                    const float* __restrict__ bias) {
    __shared__ float red[128];
    int v = blockIdx.x;
    int t = threadIdx.x;
    const float4* h4 = (const float4*)h;
    float dv = g_dinv[v];
    int beg = g_rowstart[v], end = beg + g_degcnt[v];

    float4 hv = h4[(size_t)v * (HID / 4) + t];
    float sl = dv * dv;
    float4 acc = make_float4(sl * hv.x, sl * hv.y, sl * hv.z, sl * hv.w);
    for (int j = beg; j < end; j++) {
        int s = g_adjout[j];
        float nm = dv * g_dinv[s];
        float4 hs = h4[(size_t)s * (HID / 4) + t];
        acc.x += nm * hs.x; acc.y += nm * hs.y;
        acc.z += nm * hs.z; acc.w += nm * hs.w;
    }
    float4 bb = *(const float4*)(bias + t * 4);
    acc.x = fmaxf(acc.x + bb.x, 0.0f);
    acc.y = fmaxf(acc.y + bb.y, 0.0f);
    acc.z = fmaxf(acc.z + bb.z, 0.0f);
    acc.w = fmaxf(acc.w + bb.w, 0.0f);

    // row max (values >= 0 post-relu)
    red[t] = fmaxf(fmaxf(acc.x, acc.y), fmaxf(acc.z, acc.w));
    __syncthreads();
    for (int o = 64; o > 0; o >>= 1) {
        if (t < o) red[t] = fmaxf(red[t], red[t + o]);
        __syncthreads();
    }
    float mx = red[0];
    float inv = (mx > 1e-30f) ? (QMAX / mx) : 0.0f;
    int q1x, q0x, q1y, q0y, q1z, q0z, q1w, q0w;
    quant2(acc.x, inv, q1x, q0x); quant2(acc.y, inv, q1y, q0y);
    quant2(acc.z, inv, q1z, q0z); quant2(acc.w, inv, q1w, q0w);
    size_t o4 = (size_t)v * HID + t * 4;
    *(char4*)&g_aq1[o4] = make_char4((char)q1x, (char)q1y, (char)q1z, (char)q1w);
    *(char4*)&g_aq0[o4] = make_char4((char)q0x, (char)q0y, (char)q0z, (char)q0w);
    if (t == 0) g_sa2[v] = mx / QMAX;
}

// ---------------- aggregation layer 2: gather + bias + relu (fp32) ----------
__global__ __launch_bounds__(128) void agg_f32_kernel(const float* __restrict__ h,
                                                      const float* __restrict__ bias,
                                                      float* __restrict__ outp) {
    int v = blockIdx.x;
    int t = threadIdx.x;
    const float4* h4 = (const float4*)h;
    float dv = g_dinv[v];
    int beg = g_rowstart[v], end = beg + g_degcnt[v];

    float4 hv = h4[(size_t)v * (HID / 4) + t];
    float sl = dv * dv;
    float4 acc = make_float4(sl * hv.x, sl * hv.y, sl * hv.z, sl * hv.w);
    for (int j = beg; j < end; j++) {
        int s = g_adjout[j];
        float nm = dv * g_dinv[s];
        float4 hs = h4[(size_t)s * (HID / 4) + t];
        acc.x += nm * hs.x; acc.y += nm * hs.y;
        acc.z += nm * hs.z; acc.w += nm * hs.w;
    }
    float4 bb = *(const float4*)(bias + t * 4);
    acc.x = fmaxf(acc.x + bb.x, 0.0f);
    acc.y = fmaxf(acc.y + bb.y, 0.0f);
    acc.z = fmaxf(acc.z + bb.z, 0.0f);
    acc.w = fmaxf(acc.w + bb.w, 0.0f);
    *(float4*)(outp + (size_t)v * HID + t * 4) = acc;
}

// ---------------- final logits ----------------
__global__ __launch_bounds__(256) void final_gemm(const float* __restrict__ h,
                                                  const float* __restrict__ Wl,
                                                  const float* __restrict__ bl,
                                                  float* __restrict__ out, int M) {
    __shared__ float Ws[HID][NOUT];
    int tx = threadIdx.x;
    int ty = threadIdx.y;
    int tid = ty * 16 + tx;
    for (int i = tid; i < HID * NOUT; i += 256)
        Ws[i / NOUT][i % NOUT] = Wl[i];
    __syncthreads();

    int r = blockIdx.x * 16 + ty;
    if (r >= M) return;
    const float* hr = h + (size_t)r * HID;
    float acc = bl[tx];
#pragma unroll 8
    for (int k = 0; k < HID; k++)
        acc += hr[k] * Ws[k][tx];
    out[(size_t)r * NOUT + tx] = acc;
}

// ---------------- host launch ----------------
extern "C" void kernel_launch(void* const* d_in, const int* in_sizes, int n_in,
                              void* d_out, int out_size) {
    const float* x  = (const float*)d_in[0];
    const void*  ei = d_in[1];
    const float* W1 = (const float*)d_in[2];
    const float* b1 = (const float*)d_in[3];
    const float* W2 = (const float*)d_in[4];
    const float* b2 = (const float*)d_in[5];
    const float* Wl = (const float*)d_in[6];
    const float* bl = (const float*)d_in[7];
    float* out = (float*)d_out;

    int M = in_sizes[0] / HID;
    int E = in_sizes[1] / 2;

    void *p_h, *p_a, *p_xq1, *p_xq0, *p_aq1, *p_aq0;
    void *p_bq1, *p_bq0, *p_sa1, *p_sa2, *p_sb;
    cudaGetSymbolAddress(&p_h, g_h);
    cudaGetSymbolAddress(&p_a, g_a);
    cudaGetSymbolAddress(&p_xq1, g_xq1);
    cudaGetSymbolAddress(&p_xq0, g_xq0);
    cudaGetSymbolAddress(&p_aq1, g_aq1);
    cudaGetSymbolAddress(&p_aq0, g_aq0);
    cudaGetSymbolAddress(&p_bq1, g_bq1);
    cudaGetSymbolAddress(&p_bq0, g_bq0);
    cudaGetSymbolAddress(&p_sa1, g_sa1);
    cudaGetSymbolAddress(&p_sa2, g_sa2);
    cudaGetSymbolAddress(&p_sb, g_sb);

    const int GEMM_SMEM = 2 * STAGEB;   // 81920 bytes
    cudaFuncSetAttribute(gemm_imma, cudaFuncAttributeMaxDynamicSharedMemorySize, GEMM_SMEM);

    // 0: x row-quant + zero counters/wmax
    xq_kernel<<<M, 128>>>(x);
    // 1: W column abs-max
    wmax_kernel<<<dim3(8, 2), 512>>>(W1, W2);
    // 2: W transpose + quantize
    wq_kernel<<<dim3(16, 16, 2), dim3(32, 8)>>>(W1, W2);
    // 3: edges
    convert_kernel<<<(E + 255) / 256, 256>>>(ei, E);
    // 4: row starts + dinv
    rowstart_kernel<<<(M + 255) / 256, 256>>>(M);
    // 5: adjacency fill
    fill_kernel<<<(E + 255) / 256, 256>>>(E);

    dim3 ggrid(HID / 128, (M + 127) / 128);

    // 6: layer-1 GEMM
    gemm_imma<<<ggrid, 256, GEMM_SMEM>>>((const char*)p_xq1, (const char*)p_xq0,
                                         (const char*)p_bq1, (const char*)p_bq0,
                                         (const float*)p_sa1, (const float*)p_sb,
                                         (float*)p_h, M);
    // 7: agg1 + quantize
    agg_q_kernel<<<M, 128>>>((const float*)p_h, b1);
    // 8: layer-2 GEMM
    gemm_imma<<<ggrid, 256, GEMM_SMEM>>>((const char*)p_aq1, (const char*)p_aq0,
                                         (const char*)p_bq1 + (size_t)HID * HID,
                                         (const char*)p_bq0 + (size_t)HID * HID,
                                         (const float*)p_sa2, (const float*)p_sb + HID,
                                         (float*)p_h, M);
    // 9: agg2 (fp32)
    agg_f32_kernel<<<M, 128>>>((const float*)p_h, b2, (float*)p_a);
    // 10: logits
    final_gemm<<<(M + 15) / 16, dim3(16, 16)>>>((const float*)p_a, Wl, bl, out, M);
}

// round 8
// speedup vs baseline: 2.8378x; 2.8378x over previous
#include <cuda_runtime.h>
#include <cuda_bf16.h>
#include <cstdint>

#define NNODES 10000
#define NEDGES 160000
#define HID    512
#define NOUT   16

// ---------------- device scratch ----------------
__device__ float g_h[NNODES * HID];            // GEMM output fp32
__device__ float g_a[NNODES * HID];            // layer-2 agg output fp32
__device__ __nv_bfloat16 g_xh[NNODES * HID];   // x hi
__device__ __nv_bfloat16 g_xl[NNODES * HID];   // x lo
__device__ __nv_bfloat16 g_ah[NNODES * HID];   // agg1 out hi
__device__ __nv_bfloat16 g_al[NNODES * HID];   // agg1 out lo
__device__ __nv_bfloat16 g_w1h[HID * HID], g_w1l[HID * HID];  // W1^T hi/lo
__device__ __nv_bfloat16 g_w2h[HID * HID], g_w2l[HID * HID];  // W2^T hi/lo
__device__ float g_dinv[NNODES];
__device__ int   g_degcnt[NNODES];
__device__ int   g_fill[NNODES];
__device__ int   g_rowstart[NNODES];
__device__ int   g_total;
__device__ int   g_srcv[NEDGES];
__device__ int   g_dsttmp[NEDGES];
__device__ int   g_adjout[NEDGES];

__device__ __forceinline__ uint32_t smem_to_u32(const void* p) {
    uint32_t a;
    asm("{ .reg .u64 t; cvta.to.shared.u64 t, %1; cvt.u32.u64 %0, t; }" : "=r"(a) : "l"(p));
    return a;
}

__device__ __forceinline__ void cp_async16(uint32_t dst, const void* src, bool pred) {
    int sz = pred ? 16 : 0;
    asm volatile("cp.async.cg.shared.global [%0], [%1], 16, %2;\n"
                 :: "r"(dst), "l"(src), "r"(sz));
}
__device__ __forceinline__ void cp_commit() {
    asm volatile("cp.async.commit_group;\n" ::: "memory");
}
template <int N>
__device__ __forceinline__ void cp_wait() {
    asm volatile("cp.async.wait_group %0;\n" :: "n"(N) : "memory");
}

__device__ __forceinline__ void ldsm4(uint32_t addr, uint32_t r[4]) {
    asm volatile("ldmatrix.sync.aligned.m8n8.x4.shared.b16 {%0,%1,%2,%3}, [%4];"
                 : "=r"(r[0]), "=r"(r[1]), "=r"(r[2]), "=r"(r[3]) : "r"(addr));
}

// ---------------- launch 0: x hi/lo split + zero counters ----------------
__global__ void xconv_kernel(const float* __restrict__ x, int n4) {
    int i = blockIdx.x * blockDim.x + threadIdx.x;
    if (i < NNODES) { g_degcnt[i] = 0; g_fill[i] = 0; }
    if (i == 0) g_total = 0;
    if (i >= n4) return;
    float4 v = ((const float4*)x)[i];
    __nv_bfloat16 h0 = __float2bfloat16(v.x), h1 = __float2bfloat16(v.y);
    __nv_bfloat16 h2 = __float2bfloat16(v.z), h3 = __float2bfloat16(v.w);
    __nv_bfloat16 l0 = __float2bfloat16(v.x - __bfloat162float(h0));
    __nv_bfloat16 l1 = __float2bfloat16(v.y - __bfloat162float(h1));
    __nv_bfloat16 l2 = __float2bfloat16(v.z - __bfloat162float(h2));
    __nv_bfloat16 l3 = __float2bfloat16(v.w - __bfloat162float(h3));
    ((__nv_bfloat162*)g_xh)[i * 2]     = __nv_bfloat162(h0, h1);
    ((__nv_bfloat162*)g_xh)[i * 2 + 1] = __nv_bfloat162(h2, h3);
    ((__nv_bfloat162*)g_xl)[i * 2]     = __nv_bfloat162(l0, l1);
    ((__nv_bfloat162*)g_xl)[i * 2 + 1] = __nv_bfloat162(l2, l3);
}

// ---------------- launch 1: both weight transposes + hi/lo split ----------------
__global__ void wconv_kernel(const float* __restrict__ W1,
                             const float* __restrict__ W2) {
    __shared__ float tile[32][33];
    const float* W = blockIdx.z ? W2 : W1;
    __nv_bfloat16* Th = blockIdx.z ? g_w2h : g_w1h;
    __nv_bfloat16* Tl = blockIdx.z ? g_w2l : g_w1l;
    int n0 = blockIdx.x * 32, k0 = blockIdx.y * 32;
    int tx = threadIdx.x, ty = threadIdx.y;
#pragma unroll
    for (int j = 0; j < 32; j += 8)
        tile[ty + j][tx] = W[(size_t)(k0 + ty + j) * HID + n0 + tx];
    __syncthreads();
#pragma unroll
    for (int j = 0; j < 32; j += 8) {
        float v = tile[tx][ty + j];
        __nv_bfloat16 h = __float2bfloat16(v);
        __nv_bfloat16 l = __float2bfloat16(v - __bfloat162float(h));
        size_t o = (size_t)(n0 + ty + j) * HID + k0 + tx;
        Th[o] = h; Tl[o] = l;
    }
}

// ---------------- launch 2: edge convert + degree count ----------------
__global__ void convert_kernel(const void* __restrict__ ei, int E) {
    __shared__ int s_is64;
    if (threadIdx.x == 0) {
        const unsigned int* p = (const unsigned int*)ei;
        int is64 = 1;
        for (int i = 1; i < 128; i += 2)
            if (p[i] != 0u) { is64 = 0; break; }
        s_is64 = is64;
    }
    __syncthreads();
    int e = blockIdx.x * blockDim.x + threadIdx.x;
    if (e >= E) return;
    int s, d;
    if (s_is64) {
        const long long* p = (const long long*)ei;
        s = (int)p[e]; d = (int)p[E + e];
    } else {
        const int* p = (const int*)ei;
        s = p[e]; d = p[E + e];
    }
    g_srcv[e] = s;
    g_dsttmp[e] = d;
    atomicAdd(&g_degcnt[d], 1);
}

// ---------------- launch 4: row starts (unordered CSR) + dinv ----------------
__global__ void rowstart_kernel(int M) {
    int i = blockIdx.x * blockDim.x + threadIdx.x;
    if (i >= M) return;
    int d = g_degcnt[i];
    g_dinv[i] = rsqrtf((float)d + 1.0f);
    g_rowstart[i] = atomicAdd(&g_total, d);
}

// ---------------- launch 5: adjacency fill ----------------
__global__ void fill_kernel(int E) {
    int e = blockIdx.x * blockDim.x + threadIdx.x;
    if (e >= E) return;
    int d = g_dsttmp[e];
    int s = g_srcv[e];
    int p = atomicAdd(&g_fill[d], 1);
    g_adjout[g_rowstart[d] + p] = s;
}

// ---------------- pipelined mma.sync split-bf16 GEMM ----------------
// C[M,512] = A @ B^T. Grid (4, ceil(M/128)), 256 threads = 8 warps.
// __launch_bounds__(256, 2): 2 CTAs/SM (160KB smem of 228KB) to hide latency.
#define TSTRIDE 40
#define TILEB   (128 * TSTRIDE * 2)
#define STAGEB  (4 * TILEB)

__global__ __launch_bounds__(256, 2) void gemm_mma(const __nv_bfloat16* __restrict__ Ahg,
                                                   const __nv_bfloat16* __restrict__ Alg,
                                                   const __nv_bfloat16* __restrict__ Bhg,
                                                   const __nv_bfloat16* __restrict__ Blg,
                                                   float* __restrict__ C, int M) {
    extern __shared__ char dynsm[];
    uint32_t sbase = smem_to_u32(dynsm);

    int tid = threadIdx.x;
    int wid = tid >> 5, lane = tid & 31;
    int bm = blockIdx.y * 128, bn = blockIdx.x * 128;
    int wm = (wid >> 1) * 32;
    int wn = (wid & 1) * 64;

    float acc[2][8][4];
#pragma unroll
    for (int i = 0; i < 2; i++)
#pragma unroll
        for (int n = 0; n < 8; n++)
#pragma unroll
            for (int q = 0; q < 4; q++) acc[i][n][q] = 0.0f;

    int a_row = (lane & 7) + ((lane >> 3) & 1) * 8;
    int a_col = (lane >> 4) * 8;
    int b_row = (lane & 7) + (lane >> 4) * 8;
    int b_col = ((lane >> 3) & 1) * 8;

    int row0 = tid >> 1, q0 = (tid & 1) * 2;
    bool avalid = (bm + row0) < M;

    auto issue = [&](int c, int s) {
        uint32_t st = sbase + s * STAGEB;
        size_t gA = (size_t)(bm + row0) * HID + c * 32;
        size_t gB = (size_t)(bn + row0) * HID + c * 32;
        uint32_t soff = (uint32_t)(row0 * TSTRIDE) * 2;
#pragma unroll
        for (int q = 0; q < 2; q++) {
            uint32_t dq = soff + (q0 + q) * 16;
            cp_async16(st + dq, Ahg + gA + (q0 + q) * 8, avalid);
            cp_async16(st + TILEB + dq, Alg + gA + (q0 + q) * 8, avalid);
            cp_async16(st + 2 * TILEB + dq, Bhg + gB + (q0 + q) * 8, true);
            cp_async16(st + 3 * TILEB + dq, Blg + gB + (q0 + q) * 8, true);
        }
        cp_commit();
    };

    issue(0, 0);

    for (int c = 0; c < HID / 32; c++) {
        int s = c & 1;
        if (c + 1 < HID / 32) {
            issue(c + 1, s ^ 1);
            cp_wait<1>();
        } else {
            cp_wait<0>();
        }
        __syncthreads();

        uint32_t st = sbase + s * STAGEB;
        uint32_t bAh = st, bAl = st + TILEB, bBh = st + 2 * TILEB, bBl = st + 3 * TILEB;

#pragma unroll
        for (int ks = 0; ks < 2; ks++) {
            int k0 = ks * 16;
            uint32_t ah[2][4], al[2][4], bh[4][4], bl[4][4];
#pragma unroll
            for (int i = 0; i < 2; i++) {
                uint32_t off = ((uint32_t)(wm + i * 16 + a_row) * TSTRIDE + k0 + a_col) * 2;
                ldsm4(bAh + off, ah[i]);
                ldsm4(bAl + off, al[i]);
            }
#pragma unroll
            for (int j = 0; j < 4; j++) {
                uint32_t off = ((uint32_t)(wn + j * 16 + b_row) * TSTRIDE + k0 + b_col) * 2;
                ldsm4(bBh + off, bh[j]);
                ldsm4(bBl + off, bl[j]);
            }

#pragma unroll
            for (int i = 0; i < 2; i++) {
#pragma unroll
                for (int n = 0; n < 8; n++) {
                    uint32_t h0 = bh[n >> 1][(n & 1) * 2];
                    uint32_t h1 = bh[n >> 1][(n & 1) * 2 + 1];
                    asm volatile(
                        "mma.sync.aligned.m16n8k16.row.col.f32.bf16.bf16.f32 "
                        "{%0,%1,%2,%3}, {%4,%5,%6,%7}, {%8,%9}, {%0,%1,%2,%3};"
                        : "+f"(acc[i][n][0]), "+f"(acc[i][n][1]),
                          "+f"(acc[i][n][2]), "+f"(acc[i][n][3])
                        : "r"(ah[i][0]), "r"(ah[i][1]), "r"(ah[i][2]), "r"(ah[i][3]),
                          "r"(h0), "r"(h1));
                    uint32_t l0 = bl[n >> 1][(n & 1) * 2];
                    uint32_t l1 = bl[n >> 1][(n & 1) * 2 + 1];
                    asm volatile(
                        "mma.sync.aligned.m16n8k16.row.col.f32.bf16.bf16.f32 "
                        "{%0,%1,%2,%3}, {%4,%5,%6,%7}, {%8,%9}, {%0,%1,%2,%3};"
                        : "+f"(acc[i][n][0]), "+f"(acc[i][n][1]),
                          "+f"(acc[i][n][2]), "+f"(acc[i][n][3])
                        : "r"(ah[i][0]), "r"(ah[i][1]), "r"(ah[i][2]), "r"(ah[i][3]),
                          "r"(l0), "r"(l1));
                    asm volatile(
                        "mma.sync.aligned.m16n8k16.row.col.f32.bf16.bf16.f32 "
                        "{%0,%1,%2,%3}, {%4,%5,%6,%7}, {%8,%9}, {%0,%1,%2,%3};"
                        : "+f"(acc[i][n][0]), "+f"(acc[i][n][1]),
                          "+f"(acc[i][n][2]), "+f"(acc[i][n][3])
                        : "r"(al[i][0]), "r"(al[i][1]), "r"(al[i][2]), "r"(al[i][3]),
                          "r"(h0), "r"(h1));
                }
            }
        }
        __syncthreads();
    }

#pragma unroll
    for (int i = 0; i < 2; i++) {
#pragma unroll
        for (int n = 0; n < 8; n++) {
            int r0 = bm + wm + i * 16 + (lane >> 2);
            int col = bn + wn + n * 8 + (lane & 3) * 2;
            if (r0 < M)
                *(float2*)&C[(size_t)r0 * HID + col] = make_float2(acc[i][n][0], acc[i][n][1]);
            int r1 = r0 + 8;
            if (r1 < M)
                *(float2*)&C[(size_t)r1 * HID + col] = make_float2(acc[i][n][2], acc[i][n][3]);
        }
    }
}

// ---------------- aggregation (unordered CSR gather) ----------------
__global__ __launch_bounds__(128) void agg_hl_kernel(const float* __restrict__ h,
                                                     const float* __restrict__ bias,
                                                     __nv_bfloat16* __restrict__ oh,
                                                     __nv_bfloat16* __restrict__ ol) {
    int v = blockIdx.x;
    int t = threadIdx.x;
    const float4* h4 = (const float4*)h;
    float dv = g_dinv[v];
    int beg = g_rowstart[v], end = beg + g_degcnt[v];

    float4 hv = h4[(size_t)v * (HID / 4) + t];
    float sl = dv * dv;
    float4 acc = make_float4(sl * hv.x, sl * hv.y, sl * hv.z, sl * hv.w);
    for (int j = beg; j < end; j++) {
        int s = g_adjout[j];
        float nm = dv * g_dinv[s];
        float4 hs = h4[(size_t)s * (HID / 4) + t];
        acc.x += nm * hs.x; acc.y += nm * hs.y;
        acc.z += nm * hs.z; acc.w += nm * hs.w;
    }
    float4 bb = *(const float4*)(bias + t * 4);
    acc.x = fmaxf(acc.x + bb.x, 0.0f);
    acc.y = fmaxf(acc.y + bb.y, 0.0f);
    acc.z = fmaxf(acc.z + bb.z, 0.0f);
    acc.w = fmaxf(acc.w + bb.w, 0.0f);

    __nv_bfloat16 h0 = __float2bfloat16(acc.x), h1 = __float2bfloat16(acc.y);
    __nv_bfloat16 h2 = __float2bfloat16(acc.z), h3 = __float2bfloat16(acc.w);
    __nv_bfloat16 l0 = __float2bfloat16(acc.x - __bfloat162float(h0));
    __nv_bfloat16 l1 = __float2bfloat16(acc.y - __bfloat162float(h1));
    __nv_bfloat16 l2 = __float2bfloat16(acc.z - __bfloat162float(h2));
    __nv_bfloat16 l3 = __float2bfloat16(acc.w - __bfloat162float(h3));
    size_t o2 = (size_t)v * (HID / 2) + t * 2;
    ((__nv_bfloat162*)oh)[o2]     = __nv_bfloat162(h0, h1);
    ((__nv_bfloat162*)oh)[o2 + 1] = __nv_bfloat162(h2, h3);
    ((__nv_bfloat162*)ol)[o2]     = __nv_bfloat162(l0, l1);
    ((__nv_bfloat162*)ol)[o2 + 1] = __nv_bfloat162(l2, l3);
}

__global__ __launch_bounds__(128) void agg_f32_kernel(const float* __restrict__ h,
                                                      const float* __restrict__ bias,
                                                      float* __restrict__ outp) {
    int v = blockIdx.x;
    int t = threadIdx.x;
    const float4* h4 = (const float4*)h;
    float dv = g_dinv[v];
    int beg = g_rowstart[v], end = beg + g_degcnt[v];

    float4 hv = h4[(size_t)v * (HID / 4) + t];
    float sl = dv * dv;
    float4 acc = make_float4(sl * hv.x, sl * hv.y, sl * hv.z, sl * hv.w);
    for (int j = beg; j < end; j++) {
        int s = g_adjout[j];
        float nm = dv * g_dinv[s];
        float4 hs = h4[(size_t)s * (HID / 4) + t];
        acc.x += nm * hs.x; acc.y += nm * hs.y;
        acc.z += nm * hs.z; acc.w += nm * hs.w;
    }
    float4 bb = *(const float4*)(bias + t * 4);
    acc.x = fmaxf(acc.x + bb.x, 0.0f);
    acc.y = fmaxf(acc.y + bb.y, 0.0f);
    acc.z = fmaxf(acc.z + bb.z, 0.0f);
    acc.w = fmaxf(acc.w + bb.w, 0.0f);
    *(float4*)(outp + (size_t)v * HID + t * 4) = acc;
}

// ---------------- final logits ----------------
__global__ __launch_bounds__(256) void final_gemm(const float* __restrict__ h,
                                                  const float* __restrict__ Wl,
                                                  const float* __restrict__ bl,
                                                  float* __restrict__ out, int M) {
    __shared__ float Ws[HID][NOUT];
    int tx = threadIdx.x;
    int ty = threadIdx.y;
    int tid = ty * 16 + tx;
    for (int i = tid; i < HID * NOUT; i += 256)
        Ws[i / NOUT][i % NOUT] = Wl[i];
    __syncthreads();

    int r = blockIdx.x * 16 + ty;
    if (r >= M) return;
    const float* hr = h + (size_t)r * HID;
    float acc = bl[tx];
#pragma unroll 8
    for (int k = 0; k < HID; k++)
        acc += hr[k] * Ws[k][tx];
    out[(size_t)r * NOUT + tx] = acc;
}

// ---------------- host launch ----------------
extern "C" void kernel_launch(void* const* d_in, const int* in_sizes, int n_in,
                              void* d_out, int out_size) {
    const float* x  = (const float*)d_in[0];
    const void*  ei = d_in[1];
    const float* W1 = (const float*)d_in[2];
    const float* b1 = (const float*)d_in[3];
    const float* W2 = (const float*)d_in[4];
    const float* b2 = (const float*)d_in[5];
    const float* Wl = (const float*)d_in[6];
    const float* bl = (const float*)d_in[7];
    float* out = (float*)d_out;

    int M = in_sizes[0] / HID;
    int E = in_sizes[1] / 2;

    void *p_h, *p_a, *p_xh, *p_xl, *p_ah, *p_al;
    void *p_w1h, *p_w1l, *p_w2h, *p_w2l;
    cudaGetSymbolAddress(&p_h, g_h);
    cudaGetSymbolAddress(&p_a, g_a);
    cudaGetSymbolAddress(&p_xh, g_xh);
    cudaGetSymbolAddress(&p_xl, g_xl);
    cudaGetSymbolAddress(&p_ah, g_ah);
    cudaGetSymbolAddress(&p_al, g_al);
    cudaGetSymbolAddress(&p_w1h, g_w1h);
    cudaGetSymbolAddress(&p_w1l, g_w1l);
    cudaGetSymbolAddress(&p_w2h, g_w2h);
    cudaGetSymbolAddress(&p_w2l, g_w2l);

    const int GEMM_SMEM = 2 * STAGEB;   // 81920 bytes
    cudaFuncSetAttribute(gemm_mma, cudaFuncAttributeMaxDynamicSharedMemorySize, GEMM_SMEM);

    int n4 = M * HID / 4;
    dim3 ggrid(HID / 128, (M + 127) / 128);

    // launch 0: x split + zero counters
    xconv_kernel<<<(n4 + 255) / 256, 256>>>(x, n4);
    // launch 1: both weight transposes
    wconv_kernel<<<dim3(16, 16, 2), dim3(32, 8)>>>(W1, W2);
    // launch 2: edge convert + degrees
    convert_kernel<<<(E + 255) / 256, 256>>>(ei, E);
    // launch 3: layer-1 GEMM  <-- ncu snapshot lands on our launch index 3
    gemm_mma<<<ggrid, 256, GEMM_SMEM>>>((const __nv_bfloat16*)p_xh, (const __nv_bfloat16*)p_xl,
                                        (const __nv_bfloat16*)p_w1h, (const __nv_bfloat16*)p_w1l,
                                        (float*)p_h, M);
    // launch 4: row starts + dinv
    rowstart_kernel<<<(M + 255) / 256, 256>>>(M);
    // launch 5: adjacency fill
    fill_kernel<<<(E + 255) / 256, 256>>>(E);
    // launch 6: agg1 (gather + bias + relu + hi/lo split)
    agg_hl_kernel<<<M, 128>>>((const float*)p_h, b1,
                              (__nv_bfloat16*)p_ah, (__nv_bfloat16*)p_al);
    // launch 7: layer-2 GEMM
    gemm_mma<<<ggrid, 256, GEMM_SMEM>>>((const __nv_bfloat16*)p_ah, (const __nv_bfloat16*)p_al,
                                        (const __nv_bfloat16*)p_w2h, (const __nv_bfloat16*)p_w2l,
                                        (float*)p_h, M);
    // launch 8: agg2 (fp32)
    agg_f32_kernel<<<M, 128>>>((const float*)p_h, b2, (float*)p_a);
    // launch 9: logits
    final_gemm<<<(M + 15) / 16, dim3(16, 16)>>>((const float*)p_a, Wl, bl, out, M);
}

// round 9
// speedup vs baseline: 2.8759x; 1.0134x over previous
#include <cuda_runtime.h>
#include <cuda_bf16.h>
#include <cstdint>

#define NNODES 10000
#define NEDGES 160000
#define HID    512
#define NOUT   16

// ---------------- device scratch ----------------
__device__ float g_h[NNODES * HID];            // GEMM output fp32
__device__ float g_a[NNODES * HID];            // layer-2 agg output fp32
__device__ __nv_bfloat16 g_xh[NNODES * HID];   // x hi
__device__ __nv_bfloat16 g_xl[NNODES * HID];   // x lo
__device__ __nv_bfloat16 g_ah[NNODES * HID];   // agg1 out hi
__device__ __nv_bfloat16 g_al[NNODES * HID];   // agg1 out lo
__device__ __nv_bfloat16 g_w1h[HID * HID], g_w1l[HID * HID];  // W1^T hi/lo
__device__ __nv_bfloat16 g_w2h[HID * HID], g_w2l[HID * HID];  // W2^T hi/lo
__device__ float g_dinv[NNODES];
__device__ int   g_degcnt[NNODES];
__device__ int   g_fill[NNODES];
__device__ int   g_rowstart[NNODES];
__device__ int   g_total;
__device__ int   g_srcv[NEDGES];
__device__ int   g_dsttmp[NEDGES];
__device__ int   g_adjout[NEDGES];

__device__ __forceinline__ uint32_t smem_to_u32(const void* p) {
    uint32_t a;
    asm("{ .reg .u64 t; cvta.to.shared.u64 t, %1; cvt.u32.u64 %0, t; }" : "=r"(a) : "l"(p));
    return a;
}

__device__ __forceinline__ void cp_async16(uint32_t dst, const void* src, bool pred) {
    int sz = pred ? 16 : 0;
    asm volatile("cp.async.cg.shared.global [%0], [%1], 16, %2;\n"
                 :: "r"(dst), "l"(src), "r"(sz));
}
__device__ __forceinline__ void cp_commit() {
    asm volatile("cp.async.commit_group;\n" ::: "memory");
}
template <int N>
__device__ __forceinline__ void cp_wait() {
    asm volatile("cp.async.wait_group %0;\n" :: "n"(N) : "memory");
}

__device__ __forceinline__ void ldsm4(uint32_t addr, uint32_t r[4]) {
    asm volatile("ldmatrix.sync.aligned.m8n8.x4.shared.b16 {%0,%1,%2,%3}, [%4];"
                 : "=r"(r[0]), "=r"(r[1]), "=r"(r[2]), "=r"(r[3]) : "r"(addr));
}

// ---------------- launch 0: x hi/lo split + zero counters ----------------
__global__ void xconv_kernel(const float* __restrict__ x, int n4) {
    int i = blockIdx.x * blockDim.x + threadIdx.x;
    if (i < NNODES) { g_degcnt[i] = 0; g_fill[i] = 0; }
    if (i == 0) g_total = 0;
    if (i >= n4) return;
    float4 v = ((const float4*)x)[i];
    __nv_bfloat16 h0 = __float2bfloat16(v.x), h1 = __float2bfloat16(v.y);
    __nv_bfloat16 h2 = __float2bfloat16(v.z), h3 = __float2bfloat16(v.w);
    __nv_bfloat16 l0 = __float2bfloat16(v.x - __bfloat162float(h0));
    __nv_bfloat16 l1 = __float2bfloat16(v.y - __bfloat162float(h1));
    __nv_bfloat16 l2 = __float2bfloat16(v.z - __bfloat162float(h2));
    __nv_bfloat16 l3 = __float2bfloat16(v.w - __bfloat162float(h3));
    ((__nv_bfloat162*)g_xh)[i * 2]     = __nv_bfloat162(h0, h1);
    ((__nv_bfloat162*)g_xh)[i * 2 + 1] = __nv_bfloat162(h2, h3);
    ((__nv_bfloat162*)g_xl)[i * 2]     = __nv_bfloat162(l0, l1);
    ((__nv_bfloat162*)g_xl)[i * 2 + 1] = __nv_bfloat162(l2, l3);
}

// ---------------- launch 1: both weight transposes + hi/lo split ----------------
__global__ void wconv_kernel(const float* __restrict__ W1,
                             const float* __restrict__ W2) {
    __shared__ float tile[32][33];
    const float* W = blockIdx.z ? W2 : W1;
    __nv_bfloat16* Th = blockIdx.z ? g_w2h : g_w1h;
    __nv_bfloat16* Tl = blockIdx.z ? g_w2l : g_w1l;
    int n0 = blockIdx.x * 32, k0 = blockIdx.y * 32;
    int tx = threadIdx.x, ty = threadIdx.y;
#pragma unroll
    for (int j = 0; j < 32; j += 8)
        tile[ty + j][tx] = W[(size_t)(k0 + ty + j) * HID + n0 + tx];
    __syncthreads();
#pragma unroll
    for (int j = 0; j < 32; j += 8) {
        float v = tile[tx][ty + j];
        __nv_bfloat16 h = __float2bfloat16(v);
        __nv_bfloat16 l = __float2bfloat16(v - __bfloat162float(h));
        size_t o = (size_t)(n0 + ty + j) * HID + k0 + tx;
        Th[o] = h; Tl[o] = l;
    }
}

// ---------------- launch 2: edge convert + degree count ----------------
__global__ void convert_kernel(const void* __restrict__ ei, int E) {
    __shared__ int s_is64;
    if (threadIdx.x == 0) {
        const unsigned int* p = (const unsigned int*)ei;
        int is64 = 1;
        for (int i = 1; i < 128; i += 2)
            if (p[i] != 0u) { is64 = 0; break; }
        s_is64 = is64;
    }
    __syncthreads();
    int e = blockIdx.x * blockDim.x + threadIdx.x;
    if (e >= E) return;
    int s, d;
    if (s_is64) {
        const long long* p = (const long long*)ei;
        s = (int)p[e]; d = (int)p[E + e];
    } else {
        const int* p = (const int*)ei;
        s = p[e]; d = p[E + e];
    }
    g_srcv[e] = s;
    g_dsttmp[e] = d;
    atomicAdd(&g_degcnt[d], 1);
}

// ---------------- row starts (unordered CSR) + dinv ----------------
__global__ void rowstart_kernel(int M) {
    int i = blockIdx.x * blockDim.x + threadIdx.x;
    if (i >= M) return;
    int d = g_degcnt[i];
    g_dinv[i] = rsqrtf((float)d + 1.0f);
    g_rowstart[i] = atomicAdd(&g_total, d);
}

// ---------------- adjacency fill ----------------
__global__ void fill_kernel(int E) {
    int e = blockIdx.x * blockDim.x + threadIdx.x;
    if (e >= E) return;
    int d = g_dsttmp[e];
    int s = g_srcv[e];
    int p = atomicAdd(&g_fill[d], 1);
    g_adjout[g_rowstart[d] + p] = s;
}

// ---------------- pipelined mma.sync split-bf16 GEMM ----------------
// C[M,512] = A @ B^T. Grid (4, ceil(M/128)), 512 threads = 16 warps.
// Warp tile 32(M) x 32(N); 2 CTAs/SM => 32 resident warps/SM for latency hiding.
#define TSTRIDE 40
#define TILEB   (128 * TSTRIDE * 2)
#define STAGEB  (4 * TILEB)

__global__ __launch_bounds__(512, 2) void gemm_mma(const __nv_bfloat16* __restrict__ Ahg,
                                                   const __nv_bfloat16* __restrict__ Alg,
                                                   const __nv_bfloat16* __restrict__ Bhg,
                                                   const __nv_bfloat16* __restrict__ Blg,
                                                   float* __restrict__ C, int M) {
    extern __shared__ char dynsm[];
    uint32_t sbase = smem_to_u32(dynsm);

    int tid = threadIdx.x;
    int wid = tid >> 5, lane = tid & 31;
    int bm = blockIdx.y * 128, bn = blockIdx.x * 128;
    int wm = (wid >> 2) * 32;     // 4 warp rows
    int wn = (wid & 3) * 32;      // 4 warp cols

    float acc[2][4][4];
#pragma unroll
    for (int i = 0; i < 2; i++)
#pragma unroll
        for (int n = 0; n < 4; n++)
#pragma unroll
            for (int q = 0; q < 4; q++) acc[i][n][q] = 0.0f;

    int a_row = (lane & 7) + ((lane >> 3) & 1) * 8;
    int a_col = (lane >> 4) * 8;
    int b_row = (lane & 7) + (lane >> 4) * 8;
    int b_col = ((lane >> 3) & 1) * 8;

    // copy map: 512 threads, 1 quad (16B) per tile per thread
    int row0 = tid >> 2, q0 = tid & 3;
    bool avalid = (bm + row0) < M;

    auto issue = [&](int c, int s) {
        uint32_t st = sbase + s * STAGEB;
        size_t gA = (size_t)(bm + row0) * HID + c * 32 + q0 * 8;
        size_t gB = (size_t)(bn + row0) * HID + c * 32 + q0 * 8;
        uint32_t dq = (uint32_t)(row0 * TSTRIDE) * 2 + q0 * 16;
        cp_async16(st + dq, Ahg + gA, avalid);
        cp_async16(st + TILEB + dq, Alg + gA, avalid);
        cp_async16(st + 2 * TILEB + dq, Bhg + gB, true);
        cp_async16(st + 3 * TILEB + dq, Blg + gB, true);
        cp_commit();
    };

    issue(0, 0);

    for (int c = 0; c < HID / 32; c++) {
        int s = c & 1;
        if (c + 1 < HID / 32) {
            issue(c + 1, s ^ 1);
            cp_wait<1>();
        } else {
            cp_wait<0>();
        }
        __syncthreads();

        uint32_t st = sbase + s * STAGEB;
        uint32_t bAh = st, bAl = st + TILEB, bBh = st + 2 * TILEB, bBl = st + 3 * TILEB;

#pragma unroll
        for (int ks = 0; ks < 2; ks++) {
            int k0 = ks * 16;
            uint32_t ah[2][4], al[2][4], bh[2][4], bl[2][4];
#pragma unroll
            for (int i = 0; i < 2; i++) {
                uint32_t off = ((uint32_t)(wm + i * 16 + a_row) * TSTRIDE + k0 + a_col) * 2;
                ldsm4(bAh + off, ah[i]);
                ldsm4(bAl + off, al[i]);
            }
#pragma unroll
            for (int j = 0; j < 2; j++) {
                uint32_t off = ((uint32_t)(wn + j * 16 + b_row) * TSTRIDE + k0 + b_col) * 2;
                ldsm4(bBh + off, bh[j]);
                ldsm4(bBl + off, bl[j]);
            }

#pragma unroll
            for (int i = 0; i < 2; i++) {
#pragma unroll
                for (int n = 0; n < 4; n++) {
                    uint32_t h0 = bh[n >> 1][(n & 1) * 2];
                    uint32_t h1 = bh[n >> 1][(n & 1) * 2 + 1];
                    asm volatile(
                        "mma.sync.aligned.m16n8k16.row.col.f32.bf16.bf16.f32 "
                        "{%0,%1,%2,%3}, {%4,%5,%6,%7}, {%8,%9}, {%0,%1,%2,%3};"
                        : "+f"(acc[i][n][0]), "+f"(acc[i][n][1]),
                          "+f"(acc[i][n][2]), "+f"(acc[i][n][3])
                        : "r"(ah[i][0]), "r"(ah[i][1]), "r"(ah[i][2]), "r"(ah[i][3]),
                          "r"(h0), "r"(h1));
                    uint32_t l0 = bl[n >> 1][(n & 1) * 2];
                    uint32_t l1 = bl[n >> 1][(n & 1) * 2 + 1];
                    asm volatile(
                        "mma.sync.aligned.m16n8k16.row.col.f32.bf16.bf16.f32 "
                        "{%0,%1,%2,%3}, {%4,%5,%6,%7}, {%8,%9}, {%0,%1,%2,%3};"
                        : "+f"(acc[i][n][0]), "+f"(acc[i][n][1]),
                          "+f"(acc[i][n][2]), "+f"(acc[i][n][3])
                        : "r"(ah[i][0]), "r"(ah[i][1]), "r"(ah[i][2]), "r"(ah[i][3]),
                          "r"(l0), "r"(l1));
                    asm volatile(
                        "mma.sync.aligned.m16n8k16.row.col.f32.bf16.bf16.f32 "
                        "{%0,%1,%2,%3}, {%4,%5,%6,%7}, {%8,%9}, {%0,%1,%2,%3};"
                        : "+f"(acc[i][n][0]), "+f"(acc[i][n][1]),
                          "+f"(acc[i][n][2]), "+f"(acc[i][n][3])
                        : "r"(al[i][0]), "r"(al[i][1]), "r"(al[i][2]), "r"(al[i][3]),
                          "r"(h0), "r"(h1));
                }
            }
        }
        __syncthreads();
    }

#pragma unroll
    for (int i = 0; i < 2; i++) {
#pragma unroll
        for (int n = 0; n < 4; n++) {
            int r0 = bm + wm + i * 16 + (lane >> 2);
            int col = bn + wn + n * 8 + (lane & 3) * 2;
            if (r0 < M)
                *(float2*)&C[(size_t)r0 * HID + col] = make_float2(acc[i][n][0], acc[i][n][1]);
            int r1 = r0 + 8;
            if (r1 < M)
                *(float2*)&C[(size_t)r1 * HID + col] = make_float2(acc[i][n][2], acc[i][n][3]);
        }
    }
}

// ---------------- aggregation (unordered CSR gather) ----------------
__global__ __launch_bounds__(128) void agg_hl_kernel(const float* __restrict__ h,
                                                     const float* __restrict__ bias,
                                                     __nv_bfloat16* __restrict__ oh,
                                                     __nv_bfloat16* __restrict__ ol) {
    int v = blockIdx.x;
    int t = threadIdx.x;
    const float4* h4 = (const float4*)h;
    float dv = g_dinv[v];
    int beg = g_rowstart[v], end = beg + g_degcnt[v];

    float4 hv = h4[(size_t)v * (HID / 4) + t];
    float sl = dv * dv;
    float4 acc = make_float4(sl * hv.x, sl * hv.y, sl * hv.z, sl * hv.w);
    for (int j = beg; j < end; j++) {
        int s = g_adjout[j];
        float nm = dv * g_dinv[s];
        float4 hs = h4[(size_t)s * (HID / 4) + t];
        acc.x += nm * hs.x; acc.y += nm * hs.y;
        acc.z += nm * hs.z; acc.w += nm * hs.w;
    }
    float4 bb = *(const float4*)(bias + t * 4);
    acc.x = fmaxf(acc.x + bb.x, 0.0f);
    acc.y = fmaxf(acc.y + bb.y, 0.0f);
    acc.z = fmaxf(acc.z + bb.z, 0.0f);
    acc.w = fmaxf(acc.w + bb.w, 0.0f);

    __nv_bfloat16 h0 = __float2bfloat16(acc.x), h1 = __float2bfloat16(acc.y);
    __nv_bfloat16 h2 = __float2bfloat16(acc.z), h3 = __float2bfloat16(acc.w);
    __nv_bfloat16 l0 = __float2bfloat16(acc.x - __bfloat162float(h0));
    __nv_bfloat16 l1 = __float2bfloat16(acc.y - __bfloat162float(h1));
    __nv_bfloat16 l2 = __float2bfloat16(acc.z - __bfloat162float(h2));
    __nv_bfloat16 l3 = __float2bfloat16(acc.w - __bfloat162float(h3));
    size_t o2 = (size_t)v * (HID / 2) + t * 2;
    ((__nv_bfloat162*)oh)[o2]     = __nv_bfloat162(h0, h1);
    ((__nv_bfloat162*)oh)[o2 + 1] = __nv_bfloat162(h2, h3);
    ((__nv_bfloat162*)ol)[o2]     = __nv_bfloat162(l0, l1);
    ((__nv_bfloat162*)ol)[o2 + 1] = __nv_bfloat162(l2, l3);
}

__global__ __launch_bounds__(128) void agg_f32_kernel(const float* __restrict__ h,
                                                      const float* __restrict__ bias,
                                                      float* __restrict__ outp) {
    int v = blockIdx.x;
    int t = threadIdx.x;
    const float4* h4 = (const float4*)h;
    float dv = g_dinv[v];
    int beg = g_rowstart[v], end = beg + g_degcnt[v];

    float4 hv = h4[(size_t)v * (HID / 4) + t];
    float sl = dv * dv;
    float4 acc = make_float4(sl * hv.x, sl * hv.y, sl * hv.z, sl * hv.w);
    for (int j = beg; j < end; j++) {
        int s = g_adjout[j];
        float nm = dv * g_dinv[s];
        float4 hs = h4[(size_t)s * (HID / 4) + t];
        acc.x += nm * hs.x; acc.y += nm * hs.y;
        acc.z += nm * hs.z; acc.w += nm * hs.w;
    }
    float4 bb = *(const float4*)(bias + t * 4);
    acc.x = fmaxf(acc.x + bb.x, 0.0f);
    acc.y = fmaxf(acc.y + bb.y, 0.0f);
    acc.z = fmaxf(acc.z + bb.z, 0.0f);
    acc.w = fmaxf(acc.w + bb.w, 0.0f);
    *(float4*)(outp + (size_t)v * HID + t * 4) = acc;
}

// ---------------- final logits ----------------
__global__ __launch_bounds__(256) void final_gemm(const float* __restrict__ h,
                                                  const float* __restrict__ Wl,
                                                  const float* __restrict__ bl,
                                                  float* __restrict__ out, int M) {
    __shared__ float Ws[HID][NOUT];
    int tx = threadIdx.x;
    int ty = threadIdx.y;
    int tid = ty * 16 + tx;
    for (int i = tid; i < HID * NOUT; i += 256)
        Ws[i / NOUT][i % NOUT] = Wl[i];
    __syncthreads();

    int r = blockIdx.x * 16 + ty;
    if (r >= M) return;
    const float* hr = h + (size_t)r * HID;
    float acc = bl[tx];
#pragma unroll 8
    for (int k = 0; k < HID; k++)
        acc += hr[k] * Ws[k][tx];
    out[(size_t)r * NOUT + tx] = acc;
}

// ---------------- host launch ----------------
extern "C" void kernel_launch(void* const* d_in, const int* in_sizes, int n_in,
                              void* d_out, int out_size) {
    const float* x  = (const float*)d_in[0];
    const void*  ei = d_in[1];
    const float* W1 = (const float*)d_in[2];
    const float* b1 = (const float*)d_in[3];
    const float* W2 = (const float*)d_in[4];
    const float* b2 = (const float*)d_in[5];
    const float* Wl = (const float*)d_in[6];
    const float* bl = (const float*)d_in[7];
    float* out = (float*)d_out;

    int M = in_sizes[0] / HID;
    int E = in_sizes[1] / 2;

    void *p_h, *p_a, *p_xh, *p_xl, *p_ah, *p_al;
    void *p_w1h, *p_w1l, *p_w2h, *p_w2l;
    cudaGetSymbolAddress(&p_h, g_h);
    cudaGetSymbolAddress(&p_a, g_a);
    cudaGetSymbolAddress(&p_xh, g_xh);
    cudaGetSymbolAddress(&p_xl, g_xl);
    cudaGetSymbolAddress(&p_ah, g_ah);
    cudaGetSymbolAddress(&p_al, g_al);
    cudaGetSymbolAddress(&p_w1h, g_w1h);
    cudaGetSymbolAddress(&p_w1l, g_w1l);
    cudaGetSymbolAddress(&p_w2h, g_w2h);
    cudaGetSymbolAddress(&p_w2l, g_w2l);

    const int GEMM_SMEM = 2 * STAGEB;   // 81920 bytes
    cudaFuncSetAttribute(gemm_mma, cudaFuncAttributeMaxDynamicSharedMemorySize, GEMM_SMEM);

    int n4 = M * HID / 4;
    dim3 ggrid(HID / 128, (M + 127) / 128);

    // launch 0: x split + zero counters
    xconv_kernel<<<(n4 + 255) / 256, 256>>>(x, n4);
    // launch 1: both weight transposes
    wconv_kernel<<<dim3(16, 16, 2), dim3(32, 8)>>>(W1, W2);
    // launch 2: edge convert + degrees
    convert_kernel<<<(E + 255) / 256, 256>>>(ei, E);
    // launch 3: layer-1 GEMM  <-- ncu snapshot lands here
    gemm_mma<<<ggrid, 512, GEMM_SMEM>>>((const __nv_bfloat16*)p_xh, (const __nv_bfloat16*)p_xl,
                                        (const __nv_bfloat16*)p_w1h, (const __nv_bfloat16*)p_w1l,
                                        (float*)p_h, M);
    // launch 4: row starts + dinv
    rowstart_kernel<<<(M + 255) / 256, 256>>>(M);
    // launch 5: adjacency fill
    fill_kernel<<<(E + 255) / 256, 256>>>(E);
    // launch 6: agg1
    agg_hl_kernel<<<M, 128>>>((const float*)p_h, b1,
                              (__nv_bfloat16*)p_ah, (__nv_bfloat16*)p_al);
    // launch 7: layer-2 GEMM
    gemm_mma<<<ggrid, 512, GEMM_SMEM>>>((const __nv_bfloat16*)p_ah, (const __nv_bfloat16*)p_al,
                                        (const __nv_bfloat16*)p_w2h, (const __nv_bfloat16*)p_w2l,
                                        (float*)p_h, M);
    // launch 8: agg2 (fp32)
    agg_f32_kernel<<<M, 128>>>((const float*)p_h, b2, (float*)p_a);
    // launch 9: logits
    final_gemm<<<(M + 15) / 16, dim3(16, 16)>>>((const float*)p_a, Wl, bl, out, M);
}

// round 10
// speedup vs baseline: 3.3954x; 1.1806x over previous
#include <cuda_runtime.h>
#include <cuda_fp16.h>
#include <cstdint>

#define NNODES 10000
#define NEDGES 160000
#define HID    512
#define NOUT   16

// ---------------- device scratch ----------------
__device__ float g_h[NNODES * HID];          // GEMM output fp32
__device__ float g_a[NNODES * HID];          // layer-2 agg output fp32
__device__ __half g_xh[NNODES * HID];        // x hi (fp16)
__device__ __half g_xl[NNODES * HID];        // x lo (fp16)
__device__ __half g_ah[NNODES * HID];        // agg1 out hi
__device__ __half g_al[NNODES * HID];        // agg1 out lo
__device__ __half g_w1h[HID * HID];          // W1^T fp16 (single plane)
__device__ __half g_w2h[HID * HID];          // W2^T fp16
__device__ float g_dinv[NNODES];
__device__ int   g_degcnt[NNODES];
__device__ int   g_fill[NNODES];
__device__ int   g_rowstart[NNODES];
__device__ int   g_total;
__device__ int   g_srcv[NEDGES];
__device__ int   g_dsttmp[NEDGES];
__device__ int   g_adjout[NEDGES];

__device__ __forceinline__ uint32_t smem_to_u32(const void* p) {
    uint32_t a;
    asm("{ .reg .u64 t; cvta.to.shared.u64 t, %1; cvt.u32.u64 %0, t; }" : "=r"(a) : "l"(p));
    return a;
}

__device__ __forceinline__ void cp_async16(uint32_t dst, const void* src, bool pred) {
    int sz = pred ? 16 : 0;
    asm volatile("cp.async.cg.shared.global [%0], [%1], 16, %2;\n"
                 :: "r"(dst), "l"(src), "r"(sz));
}
__device__ __forceinline__ void cp_commit() {
    asm volatile("cp.async.commit_group;\n" ::: "memory");
}
template <int N>
__device__ __forceinline__ void cp_wait() {
    asm volatile("cp.async.wait_group %0;\n" :: "n"(N) : "memory");
}

__device__ __forceinline__ void ldsm4(uint32_t addr, uint32_t r[4]) {
    asm volatile("ldmatrix.sync.aligned.m8n8.x4.shared.b16 {%0,%1,%2,%3}, [%4];"
                 : "=r"(r[0]), "=r"(r[1]), "=r"(r[2]), "=r"(r[3]) : "r"(addr));
}

__device__ __forceinline__ void mma_f16(float acc[4], const uint32_t a[4],
                                        uint32_t b0, uint32_t b1) {
    asm volatile(
        "mma.sync.aligned.m16n8k16.row.col.f32.f16.f16.f32 "
        "{%0,%1,%2,%3}, {%4,%5,%6,%7}, {%8,%9}, {%0,%1,%2,%3};"
        : "+f"(acc[0]), "+f"(acc[1]), "+f"(acc[2]), "+f"(acc[3])
        : "r"(a[0]), "r"(a[1]), "r"(a[2]), "r"(a[3]), "r"(b0), "r"(b1));
}

// ---------------- launch 0: x fp16 hi/lo split + zero counters ----------------
__global__ void xconv_kernel(const float* __restrict__ x, int n4) {
    int i = blockIdx.x * blockDim.x + threadIdx.x;
    if (i < NNODES) { g_degcnt[i] = 0; g_fill[i] = 0; }
    if (i == 0) g_total = 0;
    if (i >= n4) return;
    float4 v = ((const float4*)x)[i];
    __half h0 = __float2half(v.x), h1 = __float2half(v.y);
    __half h2 = __float2half(v.z), h3 = __float2half(v.w);
    __half l0 = __float2half(v.x - __half2float(h0));
    __half l1 = __float2half(v.y - __half2float(h1));
    __half l2 = __float2half(v.z - __half2float(h2));
    __half l3 = __float2half(v.w - __half2float(h3));
    ((__half2*)g_xh)[i * 2]     = __halves2half2(h0, h1);
    ((__half2*)g_xh)[i * 2 + 1] = __halves2half2(h2, h3);
    ((__half2*)g_xl)[i * 2]     = __halves2half2(l0, l1);
    ((__half2*)g_xl)[i * 2 + 1] = __halves2half2(l2, l3);
}

// ---------------- launch 1: both weight transposes (single fp16 plane) --------
__global__ void wconv_kernel(const float* __restrict__ W1,
                             const float* __restrict__ W2) {
    __shared__ float tile[32][33];
    const float* W = blockIdx.z ? W2 : W1;
    __half* Th = blockIdx.z ? g_w2h : g_w1h;
    int n0 = blockIdx.x * 32, k0 = blockIdx.y * 32;
    int tx = threadIdx.x, ty = threadIdx.y;
#pragma unroll
    for (int j = 0; j < 32; j += 8)
        tile[ty + j][tx] = W[(size_t)(k0 + ty + j) * HID + n0 + tx];
    __syncthreads();
#pragma unroll
    for (int j = 0; j < 32; j += 8) {
        float v = tile[tx][ty + j];
        Th[(size_t)(n0 + ty + j) * HID + k0 + tx] = __float2half(v);
    }
}

// ---------------- launch 2: edge convert + degree count ----------------
__global__ void convert_kernel(const void* __restrict__ ei, int E) {
    __shared__ int s_is64;
    if (threadIdx.x == 0) {
        const unsigned int* p = (const unsigned int*)ei;
        int is64 = 1;
        for (int i = 1; i < 128; i += 2)
            if (p[i] != 0u) { is64 = 0; break; }
        s_is64 = is64;
    }
    __syncthreads();
    int e = blockIdx.x * blockDim.x + threadIdx.x;
    if (e >= E) return;
    int s, d;
    if (s_is64) {
        const long long* p = (const long long*)ei;
        s = (int)p[e]; d = (int)p[E + e];
    } else {
        const int* p = (const int*)ei;
        s = p[e]; d = p[E + e];
    }
    g_srcv[e] = s;
    g_dsttmp[e] = d;
    atomicAdd(&g_degcnt[d], 1);
}

// ---------------- row starts (unordered CSR) + dinv ----------------
__global__ void rowstart_kernel(int M) {
    int i = blockIdx.x * blockDim.x + threadIdx.x;
    if (i >= M) return;
    int d = g_degcnt[i];
    g_dinv[i] = rsqrtf((float)d + 1.0f);
    g_rowstart[i] = atomicAdd(&g_total, d);
}

// ---------------- adjacency fill ----------------
__global__ void fill_kernel(int E) {
    int e = blockIdx.x * blockDim.x + threadIdx.x;
    if (e >= E) return;
    int d = g_dsttmp[e];
    int s = g_srcv[e];
    int p = atomicAdd(&g_fill[d], 1);
    g_adjout[g_rowstart[d] + p] = s;
}

// ---------------- 2-term split-fp16 GEMM: C[M,512] = (Ah+Al) @ Bh^T ----------
// Grid (4, ceil(M/128)), 512 threads = 16 warps, warp tile 32x32, 2 CTAs/SM.
#define TSTRIDE 40
#define TILEB   (128 * TSTRIDE * 2)   // 10240 B per 128x32 fp16 tile
#define STAGEB  (3 * TILEB)           // Ah, Al, Bh

__global__ __launch_bounds__(512, 2) void gemm_mma(const __half* __restrict__ Ahg,
                                                   const __half* __restrict__ Alg,
                                                   const __half* __restrict__ Bhg,
                                                   float* __restrict__ C, int M) {
    extern __shared__ char dynsm[];
    uint32_t sbase = smem_to_u32(dynsm);

    int tid = threadIdx.x;
    int wid = tid >> 5, lane = tid & 31;
    int bm = blockIdx.y * 128, bn = blockIdx.x * 128;
    int wm = (wid >> 2) * 32;
    int wn = (wid & 3) * 32;

    float acc[2][4][4];
#pragma unroll
    for (int i = 0; i < 2; i++)
#pragma unroll
        for (int n = 0; n < 4; n++)
#pragma unroll
            for (int q = 0; q < 4; q++) acc[i][n][q] = 0.0f;

    int a_row = (lane & 7) + ((lane >> 3) & 1) * 8;
    int a_col = (lane >> 4) * 8;
    int b_row = (lane & 7) + (lane >> 4) * 8;
    int b_col = ((lane >> 3) & 1) * 8;

    int row0 = tid >> 2, q0 = tid & 3;
    bool avalid = (bm + row0) < M;

    auto issue = [&](int c, int s) {
        uint32_t st = sbase + s * STAGEB;
        size_t gA = (size_t)(bm + row0) * HID + c * 32 + q0 * 8;
        size_t gB = (size_t)(bn + row0) * HID + c * 32 + q0 * 8;
        uint32_t dq = (uint32_t)(row0 * TSTRIDE) * 2 + q0 * 16;
        cp_async16(st + dq, Ahg + gA, avalid);
        cp_async16(st + TILEB + dq, Alg + gA, avalid);
        cp_async16(st + 2 * TILEB + dq, Bhg + gB, true);
        cp_commit();
    };

    issue(0, 0);

    for (int c = 0; c < HID / 32; c++) {
        int s = c & 1;
        if (c + 1 < HID / 32) {
            issue(c + 1, s ^ 1);
            cp_wait<1>();
        } else {
            cp_wait<0>();
        }
        __syncthreads();

        uint32_t st = sbase + s * STAGEB;
        uint32_t bAh = st, bAl = st + TILEB, bBh = st + 2 * TILEB;

#pragma unroll
        for (int ks = 0; ks < 2; ks++) {
            int k0 = ks * 16;
            uint32_t ah[2][4], al[2][4], bh[2][4];
#pragma unroll
            for (int i = 0; i < 2; i++) {
                uint32_t off = ((uint32_t)(wm + i * 16 + a_row) * TSTRIDE + k0 + a_col) * 2;
                ldsm4(bAh + off, ah[i]);
                ldsm4(bAl + off, al[i]);
            }
#pragma unroll
            for (int j = 0; j < 2; j++) {
                uint32_t off = ((uint32_t)(wn + j * 16 + b_row) * TSTRIDE + k0 + b_col) * 2;
                ldsm4(bBh + off, bh[j]);
            }

#pragma unroll
            for (int i = 0; i < 2; i++) {
#pragma unroll
                for (int n = 0; n < 4; n++) {
                    uint32_t h0 = bh[n >> 1][(n & 1) * 2];
                    uint32_t h1 = bh[n >> 1][(n & 1) * 2 + 1];
                    mma_f16(acc[i][n], ah[i], h0, h1);   // Ah * Bh
                    mma_f16(acc[i][n], al[i], h0, h1);   // Al * Bh
                }
            }
        }
        __syncthreads();
    }

#pragma unroll
    for (int i = 0; i < 2; i++) {
#pragma unroll
        for (int n = 0; n < 4; n++) {
            int r0 = bm + wm + i * 16 + (lane >> 2);
            int col = bn + wn + n * 8 + (lane & 3) * 2;
            if (r0 < M)
                *(float2*)&C[(size_t)r0 * HID + col] = make_float2(acc[i][n][0], acc[i][n][1]);
            int r1 = r0 + 8;
            if (r1 < M)
                *(float2*)&C[(size_t)r1 * HID + col] = make_float2(acc[i][n][2], acc[i][n][3]);
        }
    }
}

// ---------------- aggregation (unordered CSR gather) ----------------
__global__ __launch_bounds__(128) void agg_hl_kernel(const float* __restrict__ h,
                                                     const float* __restrict__ bias,
                                                     __half* __restrict__ oh,
                                                     __half* __restrict__ ol) {
    int v = blockIdx.x;
    int t = threadIdx.x;
    const float4* h4 = (const float4*)h;
    float dv = g_dinv[v];
    int beg = g_rowstart[v], end = beg + g_degcnt[v];

    float4 hv = h4[(size_t)v * (HID / 4) + t];
    float sl = dv * dv;
    float4 acc = make_float4(sl * hv.x, sl * hv.y, sl * hv.z, sl * hv.w);
    for (int j = beg; j < end; j++) {
        int s = g_adjout[j];
        float nm = dv * g_dinv[s];
        float4 hs = h4[(size_t)s * (HID / 4) + t];
        acc.x += nm * hs.x; acc.y += nm * hs.y;
        acc.z += nm * hs.z; acc.w += nm * hs.w;
    }
    float4 bb = *(const float4*)(bias + t * 4);
    acc.x = fmaxf(acc.x + bb.x, 0.0f);
    acc.y = fmaxf(acc.y + bb.y, 0.0f);
    acc.z = fmaxf(acc.z + bb.z, 0.0f);
    acc.w = fmaxf(acc.w + bb.w, 0.0f);

    __half h0 = __float2half(acc.x), h1 = __float2half(acc.y);
    __half h2 = __float2half(acc.z), h3 = __float2half(acc.w);
    __half l0 = __float2half(acc.x - __half2float(h0));
    __half l1 = __float2half(acc.y - __half2float(h1));
    __half l2 = __float2half(acc.z - __half2float(h2));
    __half l3 = __float2half(acc.w - __half2float(h3));
    size_t o2 = (size_t)v * (HID / 2) + t * 2;
    ((__half2*)oh)[o2]     = __halves2half2(h0, h1);
    ((__half2*)oh)[o2 + 1] = __halves2half2(h2, h3);
    ((__half2*)ol)[o2]     = __halves2half2(l0, l1);
    ((__half2*)ol)[o2 + 1] = __halves2half2(l2, l3);
}

__global__ __launch_bounds__(128) void agg_f32_kernel(const float* __restrict__ h,
                                                      const float* __restrict__ bias,
                                                      float* __restrict__ outp) {
    int v = blockIdx.x;
    int t = threadIdx.x;
    const float4* h4 = (const float4*)h;
    float dv = g_dinv[v];
    int beg = g_rowstart[v], end = beg + g_degcnt[v];

    float4 hv = h4[(size_t)v * (HID / 4) + t];
    float sl = dv * dv;
    float4 acc = make_float4(sl * hv.x, sl * hv.y, sl * hv.z, sl * hv.w);
    for (int j = beg; j < end; j++) {
        int s = g_adjout[j];
        float nm = dv * g_dinv[s];
        float4 hs = h4[(size_t)s * (HID / 4) + t];
        acc.x += nm * hs.x; acc.y += nm * hs.y;
        acc.z += nm * hs.z; acc.w += nm * hs.w;
    }
    float4 bb = *(const float4*)(bias + t * 4);
    acc.x = fmaxf(acc.x + bb.x, 0.0f);
    acc.y = fmaxf(acc.y + bb.y, 0.0f);
    acc.z = fmaxf(acc.z + bb.z, 0.0f);
    acc.w = fmaxf(acc.w + bb.w, 0.0f);
    *(float4*)(outp + (size_t)v * HID + t * 4) = acc;
}

// ---------------- final logits ----------------
__global__ __launch_bounds__(256) void final_gemm(const float* __restrict__ h,
                                                  const float* __restrict__ Wl,
                                                  const float* __restrict__ bl,
                                                  float* __restrict__ out, int M) {
    __shared__ float Ws[HID][NOUT];
    int tx = threadIdx.x;
    int ty = threadIdx.y;
    int tid = ty * 16 + tx;
    for (int i = tid; i < HID * NOUT; i += 256)
        Ws[i / NOUT][i % NOUT] = Wl[i];
    __syncthreads();

    int r = blockIdx.x * 16 + ty;
    if (r >= M) return;
    const float* hr = h + (size_t)r * HID;
    float acc = bl[tx];
#pragma unroll 8
    for (int k = 0; k < HID; k++)
        acc += hr[k] * Ws[k][tx];
    out[(size_t)r * NOUT + tx] = acc;
}

// ---------------- host launch ----------------
extern "C" void kernel_launch(void* const* d_in, const int* in_sizes, int n_in,
                              void* d_out, int out_size) {
    const float* x  = (const float*)d_in[0];
    const void*  ei = d_in[1];
    const float* W1 = (const float*)d_in[2];
    const float* b1 = (const float*)d_in[3];
    const float* W2 = (const float*)d_in[4];
    const float* b2 = (const float*)d_in[5];
    const float* Wl = (const float*)d_in[6];
    const float* bl = (const float*)d_in[7];
    float* out = (float*)d_out;

    int M = in_sizes[0] / HID;
    int E = in_sizes[1] / 2;

    void *p_h, *p_a, *p_xh, *p_xl, *p_ah, *p_al, *p_w1h, *p_w2h;
    cudaGetSymbolAddress(&p_h, g_h);
    cudaGetSymbolAddress(&p_a, g_a);
    cudaGetSymbolAddress(&p_xh, g_xh);
    cudaGetSymbolAddress(&p_xl, g_xl);
    cudaGetSymbolAddress(&p_ah, g_ah);
    cudaGetSymbolAddress(&p_al, g_al);
    cudaGetSymbolAddress(&p_w1h, g_w1h);
    cudaGetSymbolAddress(&p_w2h, g_w2h);

    const int GEMM_SMEM = 2 * STAGEB;   // 61440 bytes
    cudaFuncSetAttribute(gemm_mma, cudaFuncAttributeMaxDynamicSharedMemorySize, GEMM_SMEM);

    int n4 = M * HID / 4;
    dim3 ggrid(HID / 128, (M + 127) / 128);

    // launch 0: x split + zero counters
    xconv_kernel<<<(n4 + 255) / 256, 256>>>(x, n4);
    // launch 1: both weight transposes (fp16)
    wconv_kernel<<<dim3(16, 16, 2), dim3(32, 8)>>>(W1, W2);
    // launch 2: edge convert + degrees
    convert_kernel<<<(E + 255) / 256, 256>>>(ei, E);
    // launch 3: layer-1 GEMM  <-- ncu snapshot lands here
    gemm_mma<<<ggrid, 512, GEMM_SMEM>>>((const __half*)p_xh, (const __half*)p_xl,
                                        (const __half*)p_w1h, (float*)p_h, M);
    // launch 4: row starts + dinv
    rowstart_kernel<<<(M + 255) / 256, 256>>>(M);
    // launch 5: adjacency fill
    fill_kernel<<<(E + 255) / 256, 256>>>(E);
    // launch 6: agg1 (gather + bias + relu + fp16 hi/lo split)
    agg_hl_kernel<<<M, 128>>>((const float*)p_h, b1, (__half*)p_ah, (__half*)p_al);
    // launch 7: layer-2 GEMM
    gemm_mma<<<ggrid, 512, GEMM_SMEM>>>((const __half*)p_ah, (const __half*)p_al,
                                        (const __half*)p_w2h, (float*)p_h, M);
    // launch 8: agg2 (fp32)
    agg_f32_kernel<<<M, 128>>>((const float*)p_h, b2, (float*)p_a);
    // launch 9: logits
    final_gemm<<<(M + 15) / 16, dim3(16, 16)>>>((const float*)p_a, Wl, bl, out, M);
}

// round 12
// speedup vs baseline: 4.3413x; 1.2786x over previous
#include <cuda_runtime.h>
#include <cuda_fp16.h>
#include <cstdint>

#define NNODES 10000
#define NEDGES 160000
#define HID    512
#define NOUT   16

// ---------------- device scratch ----------------
__device__ float  g_h[NNODES * HID];         // layer-2 GEMM output fp32
__device__ __half g_hq[NNODES * HID];        // layer-1 GEMM output fp16
__device__ float  g_a[NNODES * HID];         // layer-2 agg output fp32
__device__ __half g_xq[NNODES * HID];        // x fp16
__device__ __half g_aq[NNODES * HID];        // agg1 out fp16
__device__ __half g_w1[HID * HID];           // W1^T fp16
__device__ __half g_w2[HID * HID];           // W2^T fp16
__device__ float g_dinv[NNODES];
__device__ int   g_degcnt[NNODES];
__device__ int   g_fill[NNODES];
__device__ int   g_rowstart[NNODES];
__device__ int   g_total;
__device__ int   g_srcv[NEDGES];
__device__ int   g_dsttmp[NEDGES];
__device__ int   g_adjout[NEDGES];

__device__ __forceinline__ uint32_t smem_to_u32(const void* p) {
    uint32_t a;
    asm("{ .reg .u64 t; cvta.to.shared.u64 t, %1; cvt.u32.u64 %0, t; }" : "=r"(a) : "l"(p));
    return a;
}

__device__ __forceinline__ void cp_async16(uint32_t dst, const void* src, bool pred) {
    int sz = pred ? 16 : 0;
    asm volatile("cp.async.cg.shared.global [%0], [%1], 16, %2;\n"
                 :: "r"(dst), "l"(src), "r"(sz));
}
__device__ __forceinline__ void cp_commit() {
    asm volatile("cp.async.commit_group;\n" ::: "memory");
}
template <int N>
__device__ __forceinline__ void cp_wait() {
    asm volatile("cp.async.wait_group %0;\n" :: "n"(N) : "memory");
}

__device__ __forceinline__ void ldsm4(uint32_t addr, uint32_t r[4]) {
    asm volatile("ldmatrix.sync.aligned.m8n8.x4.shared.b16 {%0,%1,%2,%3}, [%4];"
                 : "=r"(r[0]), "=r"(r[1]), "=r"(r[2]), "=r"(r[3]) : "r"(addr));
}

__device__ __forceinline__ void mma_f16(float acc[4], const uint32_t a[4],
                                        uint32_t b0, uint32_t b1) {
    asm volatile(
        "mma.sync.aligned.m16n8k16.row.col.f32.f16.f16.f32 "
        "{%0,%1,%2,%3}, {%4,%5,%6,%7}, {%8,%9}, {%0,%1,%2,%3};"
        : "+f"(acc[0]), "+f"(acc[1]), "+f"(acc[2]), "+f"(acc[3])
        : "r"(a[0]), "r"(a[1]), "r"(a[2]), "r"(a[3]), "r"(b0), "r"(b1));
}

// ---------------- launch 0: x fp16 convert + zero counters ----------------
__global__ void xconv_kernel(const float* __restrict__ x, int n4) {
    int i = blockIdx.x * blockDim.x + threadIdx.x;
    if (i < NNODES) { g_degcnt[i] = 0; g_fill[i] = 0; }
    if (i == 0) g_total = 0;
    if (i >= n4) return;
    float4 v = ((const float4*)x)[i];
    ((__half2*)g_xq)[i * 2]     = __halves2half2(__float2half(v.x), __float2half(v.y));
    ((__half2*)g_xq)[i * 2 + 1] = __halves2half2(__float2half(v.z), __float2half(v.w));
}

// ---------------- launch 1: both weight transposes (fp16) --------------------
__global__ void wconv_kernel(const float* __restrict__ W1,
                             const float* __restrict__ W2) {
    __shared__ float tile[32][33];
    const float* W = blockIdx.z ? W2 : W1;
    __half* Th = blockIdx.z ? g_w2 : g_w1;
    int n0 = blockIdx.x * 32, k0 = blockIdx.y * 32;
    int tx = threadIdx.x, ty = threadIdx.y;
#pragma unroll
    for (int j = 0; j < 32; j += 8)
        tile[ty + j][tx] = W[(size_t)(k0 + ty + j) * HID + n0 + tx];
    __syncthreads();
#pragma unroll
    for (int j = 0; j < 32; j += 8)
        Th[(size_t)(n0 + ty + j) * HID + k0 + tx] = __float2half(tile[tx][ty + j]);
}

// ---------------- launch 2: edge convert + degree count ----------------
__global__ void convert_kernel(const void* __restrict__ ei, int E) {
    __shared__ int s_is64;
    if (threadIdx.x == 0) {
        const unsigned int* p = (const unsigned int*)ei;
        int is64 = 1;
        for (int i = 1; i < 128; i += 2)
            if (p[i] != 0u) { is64 = 0; break; }
        s_is64 = is64;
    }
    __syncthreads();
    int e = blockIdx.x * blockDim.x + threadIdx.x;
    if (e >= E) return;
    int s, d;
    if (s_is64) {
        const long long* p = (const long long*)ei;
        s = (int)p[e]; d = (int)p[E + e];
    } else {
        const int* p = (const int*)ei;
        s = p[e]; d = p[E + e];
    }
    g_srcv[e] = s;
    g_dsttmp[e] = d;
    atomicAdd(&g_degcnt[d], 1);
}

// ---------------- row starts (unordered CSR) + dinv ----------------
__global__ void rowstart_kernel(int M) {
    int i = blockIdx.x * blockDim.x + threadIdx.x;
    if (i >= M) return;
    int d = g_degcnt[i];
    g_dinv[i] = rsqrtf((float)d + 1.0f);
    g_rowstart[i] = atomicAdd(&g_total, d);
}

// ---------------- adjacency fill ----------------
__global__ void fill_kernel(int E) {
    int e = blockIdx.x * blockDim.x + threadIdx.x;
    if (e >= E) return;
    int d = g_dsttmp[e];
    int s = g_srcv[e];
    int p = atomicAdd(&g_fill[d], 1);
    g_adjout[g_rowstart[d] + p] = s;
}

// ---------------- single-plane fp16 GEMM: C[M,512] = A @ B^T ----------------
// Grid (4, ceil(M/128)), 512 threads = 16 warps, warp tile 32x32, 2 CTAs/SM.
// out16: write fp16 to Cq (layer 1) else fp32 to C (layer 2).
#define TSTRIDE 40
#define TILEB   (128 * TSTRIDE * 2)   // 10240 B per 128x32 fp16 tile
#define STAGEB  (2 * TILEB)           // A, B

__global__ __launch_bounds__(512, 2) void gemm_mma(const __half* __restrict__ Ag,
                                                   const __half* __restrict__ Bg,
                                                   float* __restrict__ C,
                                                   __half* __restrict__ Cq,
                                                   int out16, int M) {
    extern __shared__ char dynsm[];
    uint32_t sbase = smem_to_u32(dynsm);

    int tid = threadIdx.x;
    int wid = tid >> 5, lane = tid & 31;
    int bm = blockIdx.y * 128, bn = blockIdx.x * 128;
    int wm = (wid >> 2) * 32;
    int wn = (wid & 3) * 32;

    float acc[2][4][4];
#pragma unroll
    for (int i = 0; i < 2; i++)
#pragma unroll
        for (int n = 0; n < 4; n++)
#pragma unroll
            for (int q = 0; q < 4; q++) acc[i][n][q] = 0.0f;

    int a_row = (lane & 7) + ((lane >> 3) & 1) * 8;
    int a_col = (lane >> 4) * 8;
    int b_row = (lane & 7) + (lane >> 4) * 8;
    int b_col = ((lane >> 3) & 1) * 8;

    int row0 = tid >> 2, q0 = tid & 3;
    bool avalid = (bm + row0) < M;

    auto issue = [&](int c, int s) {
        uint32_t st = sbase + s * STAGEB;
        size_t gA = (size_t)(bm + row0) * HID + c * 32 + q0 * 8;
        size_t gB = (size_t)(bn + row0) * HID + c * 32 + q0 * 8;
        uint32_t dq = (uint32_t)(row0 * TSTRIDE) * 2 + q0 * 16;
        cp_async16(st + dq, Ag + gA, avalid);
        cp_async16(st + TILEB + dq, Bg + gB, true);
        cp_commit();
    };

    issue(0, 0);

    for (int c = 0; c < HID / 32; c++) {
        int s = c & 1;
        if (c + 1 < HID / 32) {
            issue(c + 1, s ^ 1);
            cp_wait<1>();
        } else {
            cp_wait<0>();
        }
        __syncthreads();

        uint32_t st = sbase + s * STAGEB;
        uint32_t bA = st, bB = st + TILEB;

#pragma unroll
        for (int ks = 0; ks < 2; ks++) {
            int k0 = ks * 16;
            uint32_t af[2][4], bf[2][4];
#pragma unroll
            for (int i = 0; i < 2; i++) {
                uint32_t off = ((uint32_t)(wm + i * 16 + a_row) * TSTRIDE + k0 + a_col) * 2;
                ldsm4(bA + off, af[i]);
            }
#pragma unroll
            for (int j = 0; j < 2; j++) {
                uint32_t off = ((uint32_t)(wn + j * 16 + b_row) * TSTRIDE + k0 + b_col) * 2;
                ldsm4(bB + off, bf[j]);
            }

#pragma unroll
            for (int i = 0; i < 2; i++) {
#pragma unroll
                for (int n = 0; n < 4; n++) {
                    uint32_t h0 = bf[n >> 1][(n & 1) * 2];
                    uint32_t h1 = bf[n >> 1][(n & 1) * 2 + 1];
                    mma_f16(acc[i][n], af[i], h0, h1);
                }
            }
        }
        __syncthreads();
    }

#pragma unroll
    for (int i = 0; i < 2; i++) {
#pragma unroll
        for (int n = 0; n < 4; n++) {
            int r0 = bm + wm + i * 16 + (lane >> 2);
            int col = bn + wn + n * 8 + (lane & 3) * 2;
            int r1 = r0 + 8;
            if (out16) {
                if (r0 < M)
                    *(__half2*)&Cq[(size_t)r0 * HID + col] =
                        __halves2half2(__float2half(acc[i][n][0]), __float2half(acc[i][n][1]));
                if (r1 < M)
                    *(__half2*)&Cq[(size_t)r1 * HID + col] =
                        __halves2half2(__float2half(acc[i][n][2]), __float2half(acc[i][n][3]));
            } else {
                if (r0 < M)
                    *(float2*)&C[(size_t)r0 * HID + col] = make_float2(acc[i][n][0], acc[i][n][1]);
                if (r1 < M)
                    *(float2*)&C[(size_t)r1 * HID + col] = make_float2(acc[i][n][2], acc[i][n][3]);
            }
        }
    }
}

// ---------------- agg1: fp16 gather + bias + relu -> fp16 out ----------------
__global__ __launch_bounds__(128) void agg1_kernel(const __half* __restrict__ h,
                                                   const float* __restrict__ bias,
                                                   __half* __restrict__ oq) {
    int v = blockIdx.x;
    int t = threadIdx.x;
    const uint2* h2 = (const uint2*)h;   // 4 halves per uint2
    float dv = g_dinv[v];
    int beg = g_rowstart[v], end = beg + g_degcnt[v];

    uint2 raw = h2[(size_t)v * (HID / 4) + t];
    __half2 p0 = *(__half2*)&raw.x, p1 = *(__half2*)&raw.y;
    float sl = dv * dv;
    float4 acc;
    acc.x = sl * __low2float(p0);  acc.y = sl * __high2float(p0);
    acc.z = sl * __low2float(p1);  acc.w = sl * __high2float(p1);
    for (int j = beg; j < end; j++) {
        int s = g_adjout[j];
        float nm = dv * g_dinv[s];
        uint2 r = h2[(size_t)s * (HID / 4) + t];
        __half2 q0 = *(__half2*)&r.x, q1 = *(__half2*)&r.y;
        acc.x += nm * __low2float(q0);  acc.y += nm * __high2float(q0);
        acc.z += nm * __low2float(q1);  acc.w += nm * __high2float(q1);
    }
    float4 bb = *(const float4*)(bias + t * 4);
    acc.x = fmaxf(acc.x + bb.x, 0.0f);
    acc.y = fmaxf(acc.y + bb.y, 0.0f);
    acc.z = fmaxf(acc.z + bb.z, 0.0f);
    acc.w = fmaxf(acc.w + bb.w, 0.0f);

    size_t o2 = (size_t)v * (HID / 2) + t * 2;
    ((__half2*)oq)[o2]     = __halves2half2(__float2half(acc.x), __float2half(acc.y));
    ((__half2*)oq)[o2 + 1] = __halves2half2(__float2half(acc.z), __float2half(acc.w));
}

// ---------------- agg2: fp32 gather + bias + relu -> fp32 out ----------------
__global__ __launch_bounds__(128) void agg2_kernel(const float* __restrict__ h,
                                                   const float* __restrict__ bias,
                                                   float* __restrict__ outp) {
    int v = blockIdx.x;
    int t = threadIdx.x;
    const float4* h4 = (const float4*)h;
    float dv = g_dinv[v];
    int beg = g_rowstart[v], end = beg + g_degcnt[v];

    float4 hv = h4[(size_t)v * (HID / 4) + t];
    float sl = dv * dv;
    float4 acc = make_float4(sl * hv.x, sl * hv.y, sl * hv.z, sl * hv.w);
    for (int j = beg; j < end; j++) {
        int s = g_adjout[j];
        float nm = dv * g_dinv[s];
        float4 hs = h4[(size_t)s * (HID / 4) + t];
        acc.x += nm * hs.x; acc.y += nm * hs.y;
        acc.z += nm * hs.z; acc.w += nm * hs.w;
    }
    float4 bb = *(const float4*)(bias + t * 4);
    acc.x = fmaxf(acc.x + bb.x, 0.0f);
    acc.y = fmaxf(acc.y + bb.y, 0.0f);
    acc.z = fmaxf(acc.z + bb.z, 0.0f);
    acc.w = fmaxf(acc.w + bb.w, 0.0f);
    *(float4*)(outp + (size_t)v * HID + t * 4) = acc;
}

// ---------------- final logits ----------------
__global__ __launch_bounds__(256) void final_gemm(const float* __restrict__ h,
                                                  const float* __restrict__ Wl,
                                                  const float* __restrict__ bl,
                                                  float* __restrict__ out, int M) {
    __shared__ float Ws[HID][NOUT];
    int tx = threadIdx.x;
    int ty = threadIdx.y;
    int tid = ty * 16 + tx;
    for (int i = tid; i < HID * NOUT; i += 256)
        Ws[i / NOUT][i % NOUT] = Wl[i];
    __syncthreads();

    int r = blockIdx.x * 16 + ty;
    if (r >= M) return;
    const float* hr = h + (size_t)r * HID;
    float acc = bl[tx];
#pragma unroll 8
    for (int k = 0; k < HID; k++)
        acc += hr[k] * Ws[k][tx];
    out[(size_t)r * NOUT + tx] = acc;
}

// ---------------- host launch ----------------
extern "C" void kernel_launch(void* const* d_in, const int* in_sizes, int n_in,
                              void* d_out, int out_size) {
    const float* x  = (const float*)d_in[0];
    const void*  ei = d_in[1];
    const float* W1 = (const float*)d_in[2];
    const float* b1 = (const float*)d_in[3];
    const float* W2 = (const float*)d_in[4];
    const float* b2 = (const float*)d_in[5];
    const float* Wl = (const float*)d_in[6];
    const float* bl = (const float*)d_in[7];
    float* out = (float*)d_out;

    int M = in_sizes[0] / HID;
    int E = in_sizes[1] / 2;

    void *p_h, *p_hq, *p_a, *p_xq, *p_aq, *p_w1, *p_w2;
    cudaGetSymbolAddress(&p_h, g_h);
    cudaGetSymbolAddress(&p_hq, g_hq);
    cudaGetSymbolAddress(&p_a, g_a);
    cudaGetSymbolAddress(&p_xq, g_xq);
    cudaGetSymbolAddress(&p_aq, g_aq);
    cudaGetSymbolAddress(&p_w1, g_w1);
    cudaGetSymbolAddress(&p_w2, g_w2);

    const int GEMM_SMEM = 2 * STAGEB;   // 40960 bytes
    cudaFuncSetAttribute(gemm_mma, cudaFuncAttributeMaxDynamicSharedMemorySize, GEMM_SMEM);

    int n4 = M * HID / 4;
    dim3 ggrid(HID / 128, (M + 127) / 128);

    // launch 0: x fp16 + zero counters
    xconv_kernel<<<(n4 + 255) / 256, 256>>>(x, n4);
    // launch 1: weight transposes (fp16)
    wconv_kernel<<<dim3(16, 16, 2), dim3(32, 8)>>>(W1, W2);
    // launch 2: edge convert + degrees
    convert_kernel<<<(E + 255) / 256, 256>>>(ei, E);
    // launch 3: layer-1 GEMM (fp16 out)  <-- ncu snapshot lands here
    gemm_mma<<<ggrid, 512, GEMM_SMEM>>>((const __half*)p_xq, (const __half*)p_w1,
                                        nullptr, (__half*)p_hq, 1, M);
    // launch 4: row starts + dinv
    rowstart_kernel<<<(M + 255) / 256, 256>>>(M);
    // launch 5: adjacency fill
    fill_kernel<<<(E + 255) / 256, 256>>>(E);
    // launch 6: agg1 (fp16 gather -> fp16 out)
    agg1_kernel<<<M, 128>>>((const __half*)p_hq, b1, (__half*)p_aq);
    // launch 7: layer-2 GEMM (fp32 out)
    gemm_mma<<<ggrid, 512, GEMM_SMEM>>>((const __half*)p_aq, (const __half*)p_w2,
                                        (float*)p_h, nullptr, 0, M);
    // launch 8: agg2 (fp32)
    agg2_kernel<<<M, 128>>>((const float*)p_h, b2, (float*)p_a);
    // launch 9: logits
    final_gemm<<<(M + 15) / 16, dim3(16, 16)>>>((const float*)p_a, Wl, bl, out, M);
}

// round 13
// speedup vs baseline: 4.6118x; 1.0623x over previous
#include <cuda_runtime.h>
#include <cuda_fp16.h>
#include <cstdint>

#define NNODES 10000
#define NEDGES 160000
#define HID    512
#define NOUT   16

// ---------------- device scratch ----------------
__device__ __half g_hq[NNODES * HID];        // GEMM output fp16 (both layers)
__device__ float  g_a[NNODES * HID];         // layer-2 agg output fp32
__device__ __half g_xq[NNODES * HID];        // x fp16
__device__ __half g_aq[NNODES * HID];        // agg1 out fp16
__device__ __half g_w1[HID * HID];           // W1^T fp16
__device__ __half g_w2[HID * HID];           // W2^T fp16
__device__ float g_dinv[NNODES];
__device__ int   g_degcnt[NNODES];
__device__ int   g_fill[NNODES];
__device__ int   g_rowstart[NNODES];
__device__ int   g_total;
__device__ int   g_srcv[NEDGES];
__device__ int   g_dsttmp[NEDGES];
__device__ int   g_adjout[NEDGES];

__device__ __forceinline__ uint32_t smem_to_u32(const void* p) {
    uint32_t a;
    asm("{ .reg .u64 t; cvta.to.shared.u64 t, %1; cvt.u32.u64 %0, t; }" : "=r"(a) : "l"(p));
    return a;
}

__device__ __forceinline__ void cp_async16(uint32_t dst, const void* src, bool pred) {
    int sz = pred ? 16 : 0;
    asm volatile("cp.async.cg.shared.global [%0], [%1], 16, %2;\n"
                 :: "r"(dst), "l"(src), "r"(sz));
}
__device__ __forceinline__ void cp_commit() {
    asm volatile("cp.async.commit_group;\n" ::: "memory");
}
template <int N>
__device__ __forceinline__ void cp_wait() {
    asm volatile("cp.async.wait_group %0;\n" :: "n"(N) : "memory");
}

__device__ __forceinline__ void ldsm4(uint32_t addr, uint32_t r[4]) {
    asm volatile("ldmatrix.sync.aligned.m8n8.x4.shared.b16 {%0,%1,%2,%3}, [%4];"
                 : "=r"(r[0]), "=r"(r[1]), "=r"(r[2]), "=r"(r[3]) : "r"(addr));
}

__device__ __forceinline__ void mma_f16(float acc[4], const uint32_t a[4],
                                        uint32_t b0, uint32_t b1) {
    asm volatile(
        "mma.sync.aligned.m16n8k16.row.col.f32.f16.f16.f32 "
        "{%0,%1,%2,%3}, {%4,%5,%6,%7}, {%8,%9}, {%0,%1,%2,%3};"
        : "+f"(acc[0]), "+f"(acc[1]), "+f"(acc[2]), "+f"(acc[3])
        : "r"(a[0]), "r"(a[1]), "r"(a[2]), "r"(a[3]), "r"(b0), "r"(b1));
}

// ---------------- launch 0: fused prep (xconv | wconv | convert) -------------
// grid partition: [0, XB) xconv; [XB, XB+512) wconv; [XB+512, ...) edge convert
__global__ __launch_bounds__(256) void prep_kernel(const float* __restrict__ x,
                                                   const float* __restrict__ W1,
                                                   const float* __restrict__ W2,
                                                   const void* __restrict__ ei,
                                                   int E, int n4, int XB) {
    int b = blockIdx.x;
    int t = threadIdx.x;
    if (b < XB) {
        // ---- x fp16 convert + zero counters ----
        int i = b * 256 + t;
        if (i < NNODES) { g_degcnt[i] = 0; g_fill[i] = 0; }
        if (i == 0) g_total = 0;
        if (i >= n4) return;
        float4 v = ((const float4*)x)[i];
        ((__half2*)g_xq)[i * 2]     = __halves2half2(__float2half(v.x), __float2half(v.y));
        ((__half2*)g_xq)[i * 2 + 1] = __halves2half2(__float2half(v.z), __float2half(v.w));
    } else if (b < XB + 512) {
        // ---- W transpose + fp16 ----
        __shared__ float tile[32][33];
        int wb = b - XB;              // 0..511
        int z = wb >> 8;              // which weight
        int t16 = wb & 255;           // 16x16 tile grid
        const float* W = z ? W2 : W1;
        __half* Th = z ? g_w2 : g_w1;
        int n0 = (t16 & 15) * 32, k0 = (t16 >> 4) * 32;
#pragma unroll
        for (int j = 0; j < 4; j++) {
            int idx = t + j * 256;
            int r = idx >> 5, c = idx & 31;
            tile[r][c] = W[(size_t)(k0 + r) * HID + n0 + c];
        }
        __syncthreads();
#pragma unroll
        for (int j = 0; j < 4; j++) {
            int idx = t + j * 256;
            int r = idx >> 5, c = idx & 31;   // output row r (n-dim), col c (k-dim)
            Th[(size_t)(n0 + r) * HID + k0 + c] = __float2half(tile[c][r]);
        }
    } else {
        // ---- edge convert + degree count ----
        __shared__ int s_is64;
        if (t == 0) {
            const unsigned int* p = (const unsigned int*)ei;
            int is64 = 1;
            for (int i = 1; i < 128; i += 2)
                if (p[i] != 0u) { is64 = 0; break; }
            s_is64 = is64;
        }
        __syncthreads();
        int e = (b - XB - 512) * 256 + t;
        if (e >= E) return;
        int s, d;
        if (s_is64) {
            const long long* p = (const long long*)ei;
            s = (int)p[e]; d = (int)p[E + e];
        } else {
            const int* p = (const int*)ei;
            s = p[e]; d = p[E + e];
        }
        g_srcv[e] = s;
        g_dsttmp[e] = d;
        atomicAdd(&g_degcnt[d], 1);
    }
}

// ---------------- row starts (unordered CSR) + dinv ----------------
__global__ void rowstart_kernel(int M) {
    int i = blockIdx.x * blockDim.x + threadIdx.x;
    if (i >= M) return;
    int d = g_degcnt[i];
    g_dinv[i] = rsqrtf((float)d + 1.0f);
    g_rowstart[i] = atomicAdd(&g_total, d);
}

// ---------------- adjacency fill ----------------
__global__ void fill_kernel(int E) {
    int e = blockIdx.x * blockDim.x + threadIdx.x;
    if (e >= E) return;
    int d = g_dsttmp[e];
    int s = g_srcv[e];
    int p = atomicAdd(&g_fill[d], 1);
    g_adjout[g_rowstart[d] + p] = s;
}

// ---------------- single-plane fp16 GEMM: Cq[M,512] = A @ B^T (fp16 out) ------
// Grid (4, ceil(M/128)), 512 threads = 16 warps, warp tile 32x32, 2 CTAs/SM.
// K-chunk 64: 8 pipeline iterations, 2 barriers each.
#define KC      64
#define TSTRIDE 72                     // 64 data + 8 pad halves (144B rows)
#define TILEB   (128 * TSTRIDE * 2)    // 18432 B per 128x64 fp16 tile
#define STAGEB  (2 * TILEB)            // A, B

__global__ __launch_bounds__(512, 2) void gemm_mma(const __half* __restrict__ Ag,
                                                   const __half* __restrict__ Bg,
                                                   __half* __restrict__ Cq, int M) {
    extern __shared__ char dynsm[];
    uint32_t sbase = smem_to_u32(dynsm);

    int tid = threadIdx.x;
    int wid = tid >> 5, lane = tid & 31;
    int bm = blockIdx.y * 128, bn = blockIdx.x * 128;
    int wm = (wid >> 2) * 32;
    int wn = (wid & 3) * 32;

    float acc[2][4][4];
#pragma unroll
    for (int i = 0; i < 2; i++)
#pragma unroll
        for (int n = 0; n < 4; n++)
#pragma unroll
            for (int q = 0; q < 4; q++) acc[i][n][q] = 0.0f;

    int a_row = (lane & 7) + ((lane >> 3) & 1) * 8;
    int a_col = (lane >> 4) * 8;
    int b_row = (lane & 7) + (lane >> 4) * 8;
    int b_col = ((lane >> 3) & 1) * 8;

    // copy map: 128 rows x 8 quads per tile = 1024 quads; 512 threads -> 2 each
    int row0 = tid >> 2, q0 = (tid & 3) * 2;
    bool avalid = (bm + row0) < M;

    auto issue = [&](int c, int s) {
        uint32_t st = sbase + s * STAGEB;
        size_t gA = (size_t)(bm + row0) * HID + c * KC;
        size_t gB = (size_t)(bn + row0) * HID + c * KC;
        uint32_t so = (uint32_t)(row0 * TSTRIDE) * 2;
#pragma unroll
        for (int q = 0; q < 2; q++) {
            uint32_t dq = so + (q0 + q) * 16;
            cp_async16(st + dq, Ag + gA + (q0 + q) * 8, avalid);
            cp_async16(st + TILEB + dq, Bg + gB + (q0 + q) * 8, true);
        }
        cp_commit();
    };

    issue(0, 0);

    for (int c = 0; c < HID / KC; c++) {
        int s = c & 1;
        if (c + 1 < HID / KC) {
            issue(c + 1, s ^ 1);
            cp_wait<1>();
        } else {
            cp_wait<0>();
        }
        __syncthreads();

        uint32_t st = sbase + s * STAGEB;
        uint32_t bA = st, bB = st + TILEB;

#pragma unroll
        for (int ks = 0; ks < 4; ks++) {
            int k0 = ks * 16;
            uint32_t af[2][4], bf[2][4];
#pragma unroll
            for (int i = 0; i < 2; i++) {
                uint32_t off = ((uint32_t)(wm + i * 16 + a_row) * TSTRIDE + k0 + a_col) * 2;
                ldsm4(bA + off, af[i]);
            }
#pragma unroll
            for (int j = 0; j < 2; j++) {
                uint32_t off = ((uint32_t)(wn + j * 16 + b_row) * TSTRIDE + k0 + b_col) * 2;
                ldsm4(bB + off, bf[j]);
            }

#pragma unroll
            for (int i = 0; i < 2; i++) {
#pragma unroll
                for (int n = 0; n < 4; n++) {
                    uint32_t h0 = bf[n >> 1][(n & 1) * 2];
                    uint32_t h1 = bf[n >> 1][(n & 1) * 2 + 1];
                    mma_f16(acc[i][n], af[i], h0, h1);
                }
            }
        }
        __syncthreads();
    }

#pragma unroll
    for (int i = 0; i < 2; i++) {
#pragma unroll
        for (int n = 0; n < 4; n++) {
            int r0 = bm + wm + i * 16 + (lane >> 2);
            int col = bn + wn + n * 8 + (lane & 3) * 2;
            int r1 = r0 + 8;
            if (r0 < M)
                *(__half2*)&Cq[(size_t)r0 * HID + col] =
                    __halves2half2(__float2half(acc[i][n][0]), __float2half(acc[i][n][1]));
            if (r1 < M)
                *(__half2*)&Cq[(size_t)r1 * HID + col] =
                    __halves2half2(__float2half(acc[i][n][2]), __float2half(acc[i][n][3]));
        }
    }
}

// ---------------- agg1: fp16 gather + bias + relu -> fp16 out ----------------
__global__ __launch_bounds__(128) void agg1_kernel(const __half* __restrict__ h,
                                                   const float* __restrict__ bias,
                                                   __half* __restrict__ oq) {
    int v = blockIdx.x;
    int t = threadIdx.x;
    const uint2* h2 = (const uint2*)h;
    float dv = g_dinv[v];
    int beg = g_rowstart[v], end = beg + g_degcnt[v];

    uint2 raw = h2[(size_t)v * (HID / 4) + t];
    __half2 p0 = *(__half2*)&raw.x, p1 = *(__half2*)&raw.y;
    float sl = dv * dv;
    float4 acc;
    acc.x = sl * __low2float(p0);  acc.y = sl * __high2float(p0);
    acc.z = sl * __low2float(p1);  acc.w = sl * __high2float(p1);
    for (int j = beg; j < end; j++) {
        int s = g_adjout[j];
        float nm = dv * g_dinv[s];
        uint2 r = h2[(size_t)s * (HID / 4) + t];
        __half2 q0 = *(__half2*)&r.x, q1 = *(__half2*)&r.y;
        acc.x += nm * __low2float(q0);  acc.y += nm * __high2float(q0);
        acc.z += nm * __low2float(q1);  acc.w += nm * __high2float(q1);
    }
    float4 bb = *(const float4*)(bias + t * 4);
    acc.x = fmaxf(acc.x + bb.x, 0.0f);
    acc.y = fmaxf(acc.y + bb.y, 0.0f);
    acc.z = fmaxf(acc.z + bb.z, 0.0f);
    acc.w = fmaxf(acc.w + bb.w, 0.0f);

    size_t o2 = (size_t)v * (HID / 2) + t * 2;
    ((__half2*)oq)[o2]     = __halves2half2(__float2half(acc.x), __float2half(acc.y));
    ((__half2*)oq)[o2 + 1] = __halves2half2(__float2half(acc.z), __float2half(acc.w));
}

// ---------------- agg2: fp16 gather + bias + relu -> fp32 out ----------------
__global__ __launch_bounds__(128) void agg2_kernel(const __half* __restrict__ h,
                                                   const float* __restrict__ bias,
                                                   float* __restrict__ outp) {
    int v = blockIdx.x;
    int t = threadIdx.x;
    const uint2* h2 = (const uint2*)h;
    float dv = g_dinv[v];
    int beg = g_rowstart[v], end = beg + g_degcnt[v];

    uint2 raw = h2[(size_t)v * (HID / 4) + t];
    __half2 p0 = *(__half2*)&raw.x, p1 = *(__half2*)&raw.y;
    float sl = dv * dv;
    float4 acc;
    acc.x = sl * __low2float(p0);  acc.y = sl * __high2float(p0);
    acc.z = sl * __low2float(p1);  acc.w = sl * __high2float(p1);
    for (int j = beg; j < end; j++) {
        int s = g_adjout[j];
        float nm = dv * g_dinv[s];
        uint2 r = h2[(size_t)s * (HID / 4) + t];
        __half2 q0 = *(__half2*)&r.x, q1 = *(__half2*)&r.y;
        acc.x += nm * __low2float(q0);  acc.y += nm * __high2float(q0);
        acc.z += nm * __low2float(q1);  acc.w += nm * __high2float(q1);
    }
    float4 bb = *(const float4*)(bias + t * 4);
    acc.x = fmaxf(acc.x + bb.x, 0.0f);
    acc.y = fmaxf(acc.y + bb.y, 0.0f);
    acc.z = fmaxf(acc.z + bb.z, 0.0f);
    acc.w = fmaxf(acc.w + bb.w, 0.0f);
    *(float4*)(outp + (size_t)v * HID + t * 4) = acc;
}

// ---------------- final logits ----------------
__global__ __launch_bounds__(256) void final_gemm(const float* __restrict__ h,
                                                  const float* __restrict__ Wl,
                                                  const float* __restrict__ bl,
                                                  float* __restrict__ out, int M) {
    __shared__ float Ws[HID][NOUT];
    int tx = threadIdx.x;
    int ty = threadIdx.y;
    int tid = ty * 16 + tx;
    for (int i = tid; i < HID * NOUT; i += 256)
        Ws[i / NOUT][i % NOUT] = Wl[i];
    __syncthreads();

    int r = blockIdx.x * 16 + ty;
    if (r >= M) return;
    const float* hr = h + (size_t)r * HID;
    float acc = bl[tx];
#pragma unroll 8
    for (int k = 0; k < HID; k++)
        acc += hr[k] * Ws[k][tx];
    out[(size_t)r * NOUT + tx] = acc;
}

// ---------------- host launch ----------------
extern "C" void kernel_launch(void* const* d_in, const int* in_sizes, int n_in,
                              void* d_out, int out_size) {
    const float* x  = (const float*)d_in[0];
    const void*  ei = d_in[1];
    const float* W1 = (const float*)d_in[2];
    const float* b1 = (const float*)d_in[3];
    const float* W2 = (const float*)d_in[4];
    const float* b2 = (const float*)d_in[5];
    const float* Wl = (const float*)d_in[6];
    const float* bl = (const float*)d_in[7];
    float* out = (float*)d_out;

    int M = in_sizes[0] / HID;
    int E = in_sizes[1] / 2;

    void *p_hq, *p_a, *p_xq, *p_aq, *p_w1, *p_w2;
    cudaGetSymbolAddress(&p_hq, g_hq);
    cudaGetSymbolAddress(&p_a, g_a);
    cudaGetSymbolAddress(&p_xq, g_xq);
    cudaGetSymbolAddress(&p_aq, g_aq);
    cudaGetSymbolAddress(&p_w1, g_w1);
    cudaGetSymbolAddress(&p_w2, g_w2);

    const int GEMM_SMEM = 2 * STAGEB;   // 73728 bytes
    cudaFuncSetAttribute(gemm_mma, cudaFuncAttributeMaxDynamicSharedMemorySize, GEMM_SMEM);

    int n4 = M * HID / 4;
    int XB = (n4 + 255) / 256;
    int EB = (E + 255) / 256;
    dim3 ggrid(HID / 128, (M + 127) / 128);

    // launch 0: fused prep (xconv | wconv | edge convert)
    prep_kernel<<<XB + 512 + EB, 256>>>(x, W1, W2, ei, E, n4, XB);
    // launch 1: row starts + dinv
    rowstart_kernel<<<(M + 255) / 256, 256>>>(M);
    // launch 2: adjacency fill
    fill_kernel<<<(E + 255) / 256, 256>>>(E);
    // launch 3: layer-1 GEMM (fp16 out)  <-- ncu snapshot lands here
    gemm_mma<<<ggrid, 512, GEMM_SMEM>>>((const __half*)p_xq, (const __half*)p_w1,
                                        (__half*)p_hq, M);
    // launch 4: agg1 (fp16 gather -> fp16)
    agg1_kernel<<<M, 128>>>((const __half*)p_hq, b1, (__half*)p_aq);
    // launch 5: layer-2 GEMM (fp16 out)
    gemm_mma<<<ggrid, 512, GEMM_SMEM>>>((const __half*)p_aq, (const __half*)p_w2,
                                        (__half*)p_hq, M);
    // launch 6: agg2 (fp16 gather -> fp32)
    agg2_kernel<<<M, 128>>>((const __half*)p_hq, b2, (float*)p_a);
    // launch 7: logits
    final_gemm<<<(M + 15) / 16, dim3(16, 16)>>>((const float*)p_a, Wl, bl, out, M);
}

// round 14
// speedup vs baseline: 4.8100x; 1.0430x over previous
#include <cuda_runtime.h>
#include <cuda_fp16.h>
#include <cstdint>

#define NNODES 10000
#define NEDGES 160000
#define HID    512
#define NOUT   16

// ---------------- device scratch ----------------
__device__ __half g_hq[NNODES * HID];        // GEMM output fp16 (both layers)
__device__ __half g_xq[NNODES * HID];        // x fp16
__device__ __half g_aq[NNODES * HID];        // agg1 out fp16 / agg2 out fp16 (reused)
__device__ __half g_w1[HID * HID];           // W1^T fp16
__device__ __half g_w2[HID * HID];           // W2^T fp16
__device__ float g_dinv[NNODES];
__device__ int   g_degcnt[NNODES];
__device__ int   g_fill[NNODES];
__device__ int   g_rowstart[NNODES];
__device__ int   g_total;
__device__ int   g_srcv[NEDGES];
__device__ int   g_dsttmp[NEDGES];
__device__ int   g_adjout[NEDGES];

__device__ __forceinline__ uint32_t smem_to_u32(const void* p) {
    uint32_t a;
    asm("{ .reg .u64 t; cvta.to.shared.u64 t, %1; cvt.u32.u64 %0, t; }" : "=r"(a) : "l"(p));
    return a;
}

__device__ __forceinline__ void cp_async16(uint32_t dst, const void* src, bool pred) {
    int sz = pred ? 16 : 0;
    asm volatile("cp.async.cg.shared.global [%0], [%1], 16, %2;\n"
                 :: "r"(dst), "l"(src), "r"(sz));
}
__device__ __forceinline__ void cp_commit() {
    asm volatile("cp.async.commit_group;\n" ::: "memory");
}
template <int N>
__device__ __forceinline__ void cp_wait() {
    asm volatile("cp.async.wait_group %0;\n" :: "n"(N) : "memory");
}

__device__ __forceinline__ void ldsm4(uint32_t addr, uint32_t r[4]) {
    asm volatile("ldmatrix.sync.aligned.m8n8.x4.shared.b16 {%0,%1,%2,%3}, [%4];"
                 : "=r"(r[0]), "=r"(r[1]), "=r"(r[2]), "=r"(r[3]) : "r"(addr));
}

__device__ __forceinline__ void mma_f16(float acc[4], const uint32_t a[4],
                                        uint32_t b0, uint32_t b1) {
    asm volatile(
        "mma.sync.aligned.m16n8k16.row.col.f32.f16.f16.f32 "
        "{%0,%1,%2,%3}, {%4,%5,%6,%7}, {%8,%9}, {%0,%1,%2,%3};"
        : "+f"(acc[0]), "+f"(acc[1]), "+f"(acc[2]), "+f"(acc[3])
        : "r"(a[0]), "r"(a[1]), "r"(a[2]), "r"(a[3]), "r"(b0), "r"(b1));
}

// ---------------- launch 0: fused prep (xconv | wconv | convert) -------------
__global__ __launch_bounds__(256) void prep_kernel(const float* __restrict__ x,
                                                   const float* __restrict__ W1,
                                                   const float* __restrict__ W2,
                                                   const void* __restrict__ ei,
                                                   int E, int n4, int XB) {
    int b = blockIdx.x;
    int t = threadIdx.x;
    if (b < XB) {
        int i = b * 256 + t;
        if (i < NNODES) { g_degcnt[i] = 0; g_fill[i] = 0; }
        if (i == 0) g_total = 0;
        if (i >= n4) return;
        float4 v = ((const float4*)x)[i];
        ((__half2*)g_xq)[i * 2]     = __halves2half2(__float2half(v.x), __float2half(v.y));
        ((__half2*)g_xq)[i * 2 + 1] = __halves2half2(__float2half(v.z), __float2half(v.w));
    } else if (b < XB + 512) {
        __shared__ float tile[32][33];
        int wb = b - XB;
        int z = wb >> 8;
        int t16 = wb & 255;
        const float* W = z ? W2 : W1;
        __half* Th = z ? g_w2 : g_w1;
        int n0 = (t16 & 15) * 32, k0 = (t16 >> 4) * 32;
#pragma unroll
        for (int j = 0; j < 4; j++) {
            int idx = t + j * 256;
            int r = idx >> 5, c = idx & 31;
            tile[r][c] = W[(size_t)(k0 + r) * HID + n0 + c];
        }
        __syncthreads();
#pragma unroll
        for (int j = 0; j < 4; j++) {
            int idx = t + j * 256;
            int r = idx >> 5, c = idx & 31;
            Th[(size_t)(n0 + r) * HID + k0 + c] = __float2half(tile[c][r]);
        }
    } else {
        __shared__ int s_is64;
        if (t == 0) {
            const unsigned int* p = (const unsigned int*)ei;
            int is64 = 1;
            for (int i = 1; i < 128; i += 2)
                if (p[i] != 0u) { is64 = 0; break; }
            s_is64 = is64;
        }
        __syncthreads();
        int e = (b - XB - 512) * 256 + t;
        if (e >= E) return;
        int s, d;
        if (s_is64) {
            const long long* p = (const long long*)ei;
            s = (int)p[e]; d = (int)p[E + e];
        } else {
            const int* p = (const int*)ei;
            s = p[e]; d = p[E + e];
        }
        g_srcv[e] = s;
        g_dsttmp[e] = d;
        atomicAdd(&g_degcnt[d], 1);
    }
}

// ---------------- row starts (unordered CSR) + dinv ----------------
__global__ void rowstart_kernel(int M) {
    int i = blockIdx.x * blockDim.x + threadIdx.x;
    if (i >= M) return;
    int d = g_degcnt[i];
    g_dinv[i] = rsqrtf((float)d + 1.0f);
    g_rowstart[i] = atomicAdd(&g_total, d);
}

// ---------------- adjacency fill ----------------
__global__ void fill_kernel(int E) {
    int e = blockIdx.x * blockDim.x + threadIdx.x;
    if (e >= E) return;
    int d = g_dsttmp[e];
    int s = g_srcv[e];
    int p = atomicAdd(&g_fill[d], 1);
    g_adjout[g_rowstart[d] + p] = s;
}

// ---------------- 3-stage fp16 GEMM: Cq[M,512] = A @ B^T (fp16 out) ----------
// Grid (4, ceil(M/128)), 512 threads = 16 warps, warp tile 32x32, 2 CTAs/SM.
#define KC      32
#define NC      (HID / KC)             // 16 chunks
#define TSTRIDE 40                     // 32 data + 8 pad halves (80B rows)
#define TILEB   (128 * TSTRIDE * 2)    // 10240 B per 128x32 fp16 tile
#define STAGEB  (2 * TILEB)            // A, B per stage
#define NSTAGE  3

__global__ __launch_bounds__(512, 2) void gemm_mma(const __half* __restrict__ Ag,
                                                   const __half* __restrict__ Bg,
                                                   __half* __restrict__ Cq, int M) {
    extern __shared__ char dynsm[];
    uint32_t sbase = smem_to_u32(dynsm);

    int tid = threadIdx.x;
    int wid = tid >> 5, lane = tid & 31;
    int bm = blockIdx.y * 128, bn = blockIdx.x * 128;
    int wm = (wid >> 2) * 32;
    int wn = (wid & 3) * 32;

    float acc[2][4][4];
#pragma unroll
    for (int i = 0; i < 2; i++)
#pragma unroll
        for (int n = 0; n < 4; n++)
#pragma unroll
            for (int q = 0; q < 4; q++) acc[i][n][q] = 0.0f;

    int a_row = (lane & 7) + ((lane >> 3) & 1) * 8;
    int a_col = (lane >> 4) * 8;
    int b_row = (lane & 7) + (lane >> 4) * 8;
    int b_col = ((lane >> 3) & 1) * 8;

    // copy map: 128 rows x 4 quads per tile = 512 quads; 512 threads -> 1 each
    int row0 = tid >> 2, q0 = tid & 3;
    bool avalid = (bm + row0) < M;

    auto issue = [&](int c, int s) {
        uint32_t st = sbase + s * STAGEB;
        size_t gA = (size_t)(bm + row0) * HID + c * KC + q0 * 8;
        size_t gB = (size_t)(bn + row0) * HID + c * KC + q0 * 8;
        uint32_t dq = (uint32_t)(row0 * TSTRIDE) * 2 + q0 * 16;
        cp_async16(st + dq, Ag + gA, avalid);
        cp_async16(st + TILEB + dq, Bg + gB, true);
        cp_commit();
    };

    issue(0, 0);
    issue(1, 1);

    for (int c = 0; c < NC; c++) {
        int s = c % NSTAGE;
        if (c + 2 < NC) issue(c + 2, (c + 2) % NSTAGE);
        cp_wait<2>();
        __syncthreads();

        uint32_t st = sbase + s * STAGEB;
        uint32_t bA = st, bB = st + TILEB;

#pragma unroll
        for (int ks = 0; ks < 2; ks++) {
            int k0 = ks * 16;
            uint32_t af[2][4], bf[2][4];
#pragma unroll
            for (int i = 0; i < 2; i++) {
                uint32_t off = ((uint32_t)(wm + i * 16 + a_row) * TSTRIDE + k0 + a_col) * 2;
                ldsm4(bA + off, af[i]);
            }
#pragma unroll
            for (int j = 0; j < 2; j++) {
                uint32_t off = ((uint32_t)(wn + j * 16 + b_row) * TSTRIDE + k0 + b_col) * 2;
                ldsm4(bB + off, bf[j]);
            }

#pragma unroll
            for (int i = 0; i < 2; i++) {
#pragma unroll
                for (int n = 0; n < 4; n++) {
                    uint32_t h0 = bf[n >> 1][(n & 1) * 2];
                    uint32_t h1 = bf[n >> 1][(n & 1) * 2 + 1];
                    mma_f16(acc[i][n], af[i], h0, h1);
                }
            }
        }
        __syncthreads();
    }

#pragma unroll
    for (int i = 0; i < 2; i++) {
#pragma unroll
        for (int n = 0; n < 4; n++) {
            int r0 = bm + wm + i * 16 + (lane >> 2);
            int col = bn + wn + n * 8 + (lane & 3) * 2;
            int r1 = r0 + 8;
            if (r0 < M)
                *(__half2*)&Cq[(size_t)r0 * HID + col] =
                    __halves2half2(__float2half(acc[i][n][0]), __float2half(acc[i][n][1]));
            if (r1 < M)
                *(__half2*)&Cq[(size_t)r1 * HID + col] =
                    __halves2half2(__float2half(acc[i][n][2]), __float2half(acc[i][n][3]));
        }
    }
}

// ---------------- agg: fp16 gather + bias + relu -> fp16 out ----------------
__global__ __launch_bounds__(128) void agg_kernel(const __half* __restrict__ h,
                                                  const float* __restrict__ bias,
                                                  __half* __restrict__ oq) {
    int v = blockIdx.x;
    int t = threadIdx.x;
    const uint2* h2 = (const uint2*)h;
    float dv = g_dinv[v];
    int beg = g_rowstart[v], end = beg + g_degcnt[v];

    uint2 raw = h2[(size_t)v * (HID / 4) + t];
    __half2 p0 = *(__half2*)&raw.x, p1 = *(__half2*)&raw.y;
    float sl = dv * dv;
    float4 acc;
    acc.x = sl * __low2float(p0);  acc.y = sl * __high2float(p0);
    acc.z = sl * __low2float(p1);  acc.w = sl * __high2float(p1);
    for (int j = beg; j < end; j++) {
        int s = g_adjout[j];
        float nm = dv * g_dinv[s];
        uint2 r = h2[(size_t)s * (HID / 4) + t];
        __half2 q0 = *(__half2*)&r.x, q1 = *(__half2*)&r.y;
        acc.x += nm * __low2float(q0);  acc.y += nm * __high2float(q0);
        acc.z += nm * __low2float(q1);  acc.w += nm * __high2float(q1);
    }
    float4 bb = *(const float4*)(bias + t * 4);
    acc.x = fmaxf(acc.x + bb.x, 0.0f);
    acc.y = fmaxf(acc.y + bb.y, 0.0f);
    acc.z = fmaxf(acc.z + bb.z, 0.0f);
    acc.w = fmaxf(acc.w + bb.w, 0.0f);

    size_t o2 = (size_t)v * (HID / 2) + t * 2;
    ((__half2*)oq)[o2]     = __halves2half2(__float2half(acc.x), __float2half(acc.y));
    ((__half2*)oq)[o2 + 1] = __halves2half2(__float2half(acc.z), __float2half(acc.w));
}

// ---------------- final logits (fp16 h, fp16 Ws, fp32 accumulate) ------------
__global__ __launch_bounds__(256) void final_gemm(const __half* __restrict__ h,
                                                  const float* __restrict__ Wl,
                                                  const float* __restrict__ bl,
                                                  float* __restrict__ out, int M) {
    __shared__ __half Ws[HID][NOUT];
    int tx = threadIdx.x;   // class
    int ty = threadIdx.y;   // row within block
    int tid = ty * 16 + tx;
    for (int i = tid; i < HID * NOUT; i += 256)
        Ws[i / NOUT][i % NOUT] = __float2half(Wl[i]);
    __syncthreads();

    int r = blockIdx.x * 16 + ty;
    if (r >= M) return;
    const __half* hr = h + (size_t)r * HID;
    float acc = bl[tx];
#pragma unroll 8
    for (int k = 0; k < HID; k++)
        acc += __half2float(hr[k]) * __half2float(Ws[k][tx]);
    out[(size_t)r * NOUT + tx] = acc;
}

// ---------------- host launch ----------------
extern "C" void kernel_launch(void* const* d_in, const int* in_sizes, int n_in,
                              void* d_out, int out_size) {
    const float* x  = (const float*)d_in[0];
    const void*  ei = d_in[1];
    const float* W1 = (const float*)d_in[2];
    const float* b1 = (const float*)d_in[3];
    const float* W2 = (const float*)d_in[4];
    const float* b2 = (const float*)d_in[5];
    const float* Wl = (const float*)d_in[6];
    const float* bl = (const float*)d_in[7];
    float* out = (float*)d_out;

    int M = in_sizes[0] / HID;
    int E = in_sizes[1] / 2;

    void *p_hq, *p_xq, *p_aq, *p_w1, *p_w2;
    cudaGetSymbolAddress(&p_hq, g_hq);
    cudaGetSymbolAddress(&p_xq, g_xq);
    cudaGetSymbolAddress(&p_aq, g_aq);
    cudaGetSymbolAddress(&p_w1, g_w1);
    cudaGetSymbolAddress(&p_w2, g_w2);

    const int GEMM_SMEM = NSTAGE * STAGEB;   // 61440 bytes
    cudaFuncSetAttribute(gemm_mma, cudaFuncAttributeMaxDynamicSharedMemorySize, GEMM_SMEM);

    int n4 = M * HID / 4;
    int XB = (n4 + 255) / 256;
    int EB = (E + 255) / 256;
    dim3 ggrid(HID / 128, (M + 127) / 128);

    // launch 0: fused prep (xconv | wconv | edge convert)
    prep_kernel<<<XB + 512 + EB, 256>>>(x, W1, W2, ei, E, n4, XB);
    // launch 1: row starts + dinv
    rowstart_kernel<<<(M + 255) / 256, 256>>>(M);
    // launch 2: adjacency fill
    fill_kernel<<<(E + 255) / 256, 256>>>(E);
    // launch 3: layer-1 GEMM (fp16 out)  <-- ncu snapshot lands here
    gemm_mma<<<ggrid, 512, GEMM_SMEM>>>((const __half*)p_xq, (const __half*)p_w1,
                                        (__half*)p_hq, M);
    // launch 4: agg1 (fp16 gather -> fp16)
    agg_kernel<<<M, 128>>>((const __half*)p_hq, b1, (__half*)p_aq);
    // launch 5: layer-2 GEMM (fp16 out)
    gemm_mma<<<ggrid, 512, GEMM_SMEM>>>((const __half*)p_aq, (const __half*)p_w2,
                                        (__half*)p_hq, M);
    // launch 6: agg2 (fp16 gather -> fp16; g_aq free after gemm2 consumed it)
    agg_kernel<<<M, 128>>>((const __half*)p_hq, b2, (__half*)p_aq);
    // launch 7: logits (fp16 inputs, fp32 out)
    final_gemm<<<(M + 15) / 16, dim3(16, 16)>>>((const __half*)p_aq, Wl, bl, out, M);
}